// round 3
// baseline (speedup 1.0000x reference)
#include <cuda_runtime.h>
#include <math_constants.h>

#define BB 4
#define TT 4096
#define DD 1024
#define HH 64
#define NROW (BB*TT)

typedef unsigned long long ull;

// Scratch for projected k, q, v — __device__ globals per allocation rules.
__device__ float g_K[NROW*HH];
__device__ float g_Q[NROW*HH];
__device__ float g_V[NROW*HH];

// ---- packed f32x2 helpers (ptxas never emits these from C++) ----
__device__ __forceinline__ ull pack2(float lo, float hi) {
    ull r; asm("mov.b64 %0, {%1,%2};" : "=l"(r) : "f"(lo), "f"(hi)); return r;
}
__device__ __forceinline__ void unpack2(ull v, float& lo, float& hi) {
    asm("mov.b64 {%0,%1}, %2;" : "=f"(lo), "=f"(hi) : "l"(v));
}
__device__ __forceinline__ void ffma2(ull& d, ull a, ull b) {
    asm("fma.rn.f32x2 %0, %1, %2, %0;" : "+l"(d) : "l"(a), "l"(b));
}
__device__ __forceinline__ void mul2(ull& d, ull a) {
    asm("mul.rn.f32x2 %0, %0, %1;" : "+l"(d) : "l"(a));
}

__device__ __forceinline__ float grpmax16(float v) {
#pragma unroll
    for (int m = 8; m >= 1; m >>= 1)
        v = fmaxf(v, __shfl_xor_sync(0xffffffffu, v, m));
    return v;
}
__device__ __forceinline__ float grpsum16(float v) {
#pragma unroll
    for (int m = 8; m >= 1; m >>= 1)
        v += __shfl_xor_sync(0xffffffffu, v, m);
    return v;
}

// 4(row-pairs packed)x4 outer-product micro-kernel over 4 k-steps.
// ap: transposed+swizzled A tile at (4*k4, slot), bp: B tile row 4*k4.
__device__ __forceinline__ void gemm_step(ull (&acc)[2][4],
                                          const float* __restrict__ ap,
                                          const float* __restrict__ bp) {
#pragma unroll
    for (int kk = 0; kk < 4; kk++) {
        ulonglong2 A = *(const ulonglong2*)(ap + kk * 64);
        float4 bq = *(const float4*)(bp + kk * 64);
        ull b0 = pack2(bq.x, bq.x), b1 = pack2(bq.y, bq.y);
        ull b2 = pack2(bq.z, bq.z), b3 = pack2(bq.w, bq.w);
        ffma2(acc[0][0], A.x, b0); ffma2(acc[0][1], A.x, b1);
        ffma2(acc[0][2], A.x, b2); ffma2(acc[0][3], A.x, b3);
        ffma2(acc[1][0], A.y, b0); ffma2(acc[1][1], A.y, b1);
        ffma2(acc[1][2], A.y, b2); ffma2(acc[1][3], A.y, b3);
    }
}

// tile loaders: 256 threads, 64x64 fp32 tile, 4 float4 per thread
__device__ __forceinline__ void ldg_tile(const float* __restrict__ base,
                                         int tx, int ty, float4 (&p)[4]) {
#pragma unroll
    for (int u = 0; u < 4; u++) {
        int r = ty + 16 * u;
        p[u] = *(const float4*)(base + (size_t)r * 64 + 4 * tx);
    }
}
// store transposed + XOR swizzled: element (r, 4tx+q) -> T[4tx+q][4*((r>>2)^tx)+(r&3)]
__device__ __forceinline__ void sts_T(float* __restrict__ Tn, int tx, int ty,
                                      const float4 (&p)[4]) {
#pragma unroll
    for (int u = 0; u < 4; u++) {
        int r = ty + 16 * u;
        int col = 4 * ((r >> 2) ^ tx) + (r & 3);
        Tn[(4 * tx + 0) * 64 + col] = p[u].x;
        Tn[(4 * tx + 1) * 64 + col] = p[u].y;
        Tn[(4 * tx + 2) * 64 + col] = p[u].z;
        Tn[(4 * tx + 3) * 64 + col] = p[u].w;
    }
}
// store natural
__device__ __forceinline__ void sts_N(float* __restrict__ Nn, int tx, int ty,
                                      const float4 (&p)[4]) {
#pragma unroll
    for (int u = 0; u < 4; u++) {
        int r = ty + 16 * u;
        *(float4*)&Nn[(size_t)r * 64 + 4 * tx] = p[u];
    }
}

// ---------------------------------------------------------------------------
// QKV projection: out = x @ W + b. 64x64 CTA tile, 256 threads, 4x4 micro,
// f32x2 packed, double-buffered K-chunks (LDG prefetch overlaps compute).
// ---------------------------------------------------------------------------
__global__ __launch_bounds__(256)
void qkv_kernel(const float* __restrict__ x,
                const float* __restrict__ Wk, const float* __restrict__ bk,
                const float* __restrict__ Wq, const float* __restrict__ bq,
                const float* __restrict__ Wv, const float* __restrict__ bv)
{
    extern __shared__ float sm[];
    float* Xb[2] = { sm, sm + 4096 };            // transposed+swizzled (k, t)
    float* Wb[2] = { sm + 8192, sm + 12288 };    // natural (k, n)

    const float* W; const float* bias; float* out;
    if (blockIdx.y == 0)      { W = Wk; bias = bk; out = g_K; }
    else if (blockIdx.y == 1) { W = Wq; bias = bq; out = g_Q; }
    else                      { W = Wv; bias = bv; out = g_V; }

    const int tid = threadIdx.x;
    const int tx = tid & 15, ty = tid >> 4;
    const int row0 = blockIdx.x * 64;

    // prolog: chunk 0
    float4 px[4], pw[4];
#pragma unroll
    for (int u = 0; u < 4; u++) {
        int r = ty + 16 * u;
        px[u] = *(const float4*)(x + (size_t)(row0 + r) * DD + 4 * tx);
        pw[u] = *(const float4*)(W + (size_t)r * HH + 4 * tx);
    }
    sts_T(Xb[0], tx, ty, px);
    sts_N(Wb[0], tx, ty, pw);
    __syncthreads();

    ull acc2[2][4];
    ull zz = pack2(0.f, 0.f);
#pragma unroll
    for (int p = 0; p < 2; p++)
#pragma unroll
        for (int j = 0; j < 4; j++) acc2[p][j] = zz;

#pragma unroll 1
    for (int kc = 0; kc < 16; kc++) {
        const float* Xc = Xb[kc & 1];
        const float* Wc = Wb[kc & 1];
        if (kc < 15) {
            int k0 = (kc + 1) * 64;
#pragma unroll
            for (int u = 0; u < 4; u++) {
                int r = ty + 16 * u;
                px[u] = *(const float4*)(x + (size_t)(row0 + r) * DD + k0 + 4 * tx);
                pw[u] = *(const float4*)(W + (size_t)(k0 + r) * HH + 4 * tx);
            }
        }
#pragma unroll 1
        for (int k4 = 0; k4 < 16; k4++)
            gemm_step(acc2, &Xc[(4 * k4) * 64 + 4 * (ty ^ k4)],
                            &Wc[(4 * k4) * 64 + 4 * tx]);
        if (kc < 15) {
            __syncthreads();
            sts_T(Xb[(kc + 1) & 1], tx, ty, px);
            sts_N(Wb[(kc + 1) & 1], tx, ty, pw);
            __syncthreads();
        }
    }

    float4 bb = *(const float4*)(bias + 4 * tx);
    float a[4][4];
#pragma unroll
    for (int p = 0; p < 2; p++)
#pragma unroll
        for (int j = 0; j < 4; j++) unpack2(acc2[p][j], a[2*p][j], a[2*p+1][j]);
#pragma unroll
    for (int i = 0; i < 4; i++) {
        float4 o;
        o.x = a[i][0] + bb.x; o.y = a[i][1] + bb.y;
        o.z = a[i][2] + bb.z; o.w = a[i][3] + bb.w;
        *(float4*)(out + (size_t)(row0 + 4 * ty + i) * HH + 4 * tx) = o;
    }
}

// ---------------------------------------------------------------------------
// Causal flash attention, fp32, f32x2 packed, 64x64 tiles, 256 threads,
// 4x4 micro, double-buffered Q/V tiles (prefetch overlaps S-gemm+softmax).
// 256 CTAs in descending-work order -> LPT via work-stealing.
// ---------------------------------------------------------------------------
__global__ __launch_bounds__(256)
void attn_kernel(float* __restrict__ out)
{
    extern __shared__ float sm[];
    float* Kst   = sm;                              // (h, tslot) T+swizzled
    float* Qb[2] = { sm + 4096,  sm + 8192 };       // (h, sslot) T+swizzled
    float* Vb[2] = { sm + 12288, sm + 16384 };      // (s, h) natural
    float* Ps    = sm + 20480;                      // P^T (s, tslot) swizzled

    const int tid = threadIdx.x;
    const int tx = tid & 15, ty = tid >> 4;
    const int bid = blockIdx.x;
    const int b  = bid & 3;
    const int bt = 63 - (bid >> 2);                 // descending work order
    const size_t rowbase = (size_t)b * TT + (size_t)bt * 64;
    const size_t bQbase  = (size_t)b * TT * HH;

    // prolog: K tile + Q0/V0
    {
        float4 pk[4], pq[4], pv[4];
        ldg_tile(g_K + rowbase * HH, tx, ty, pk);
        ldg_tile(g_Q + bQbase, tx, ty, pq);
        ldg_tile(g_V + bQbase, tx, ty, pv);
        sts_T(Kst, tx, ty, pk);
        sts_T(Qb[0], tx, ty, pq);
        sts_N(Vb[0], tx, ty, pv);
    }
    __syncthreads();

    ull o2[2][4];
    ull zz = pack2(0.f, 0.f);
#pragma unroll
    for (int p = 0; p < 2; p++)
#pragma unroll
        for (int j = 0; j < 4; j++) o2[p][j] = zz;
    float mrow[4], lrow[4];
#pragma unroll
    for (int i = 0; i < 4; i++) { mrow[i] = -CUDART_INF_F; lrow[i] = 0.f; }

#pragma unroll 1
    for (int st = 0; st <= bt; st++) {
        const float* Qcur = Qb[st & 1];
        const float* Vcur = Vb[st & 1];
        const bool pf = (st < bt);

        float4 pq[4], pv[4];
        if (pf) {
            const float* qn = g_Q + bQbase + (size_t)(st + 1) * 64 * HH;
            const float* vn = g_V + bQbase + (size_t)(st + 1) * 64 * HH;
            ldg_tile(qn, tx, ty, pq);
            ldg_tile(vn, tx, ty, pv);
        }

        // ---- S = k-rows x q-cols (outer product over h) ----
        ull s2[2][4];
#pragma unroll
        for (int p = 0; p < 2; p++)
#pragma unroll
            for (int j = 0; j < 4; j++) s2[p][j] = zz;
#pragma unroll 1
        for (int k4 = 0; k4 < 16; k4++)
            gemm_step(s2, &Kst[(4 * k4) * 64 + 4 * (ty ^ k4)],
                           &Qcur[(4 * k4) * 64 + 4 * (tx ^ k4)]);

        float s[4][4];
#pragma unroll
        for (int p = 0; p < 2; p++)
#pragma unroll
            for (int j = 0; j < 4; j++) unpack2(s2[p][j], s[2*p][j], s[2*p+1][j]);

        const float scale = 0.125f;    // 1/sqrt(64)
        if (st == bt) {
#pragma unroll
            for (int i = 0; i < 4; i++)
#pragma unroll
                for (int j = 0; j < 4; j++) {
                    int r = 4 * ty + i, c = 4 * tx + j;
                    s[i][j] = (c <= r) ? s[i][j] * scale : -1e30f;
                }
        } else {
#pragma unroll
            for (int i = 0; i < 4; i++)
#pragma unroll
                for (int j = 0; j < 4; j++) s[i][j] *= scale;
        }

        // ---- online softmax across the 16 tx lanes ----
        float corr[4];
#pragma unroll
        for (int i = 0; i < 4; i++) {
            float rm = fmaxf(fmaxf(s[i][0], s[i][1]), fmaxf(s[i][2], s[i][3]));
            rm = grpmax16(rm);
            float mnew = fmaxf(mrow[i], rm);
            corr[i] = __expf(mrow[i] - mnew);
            mrow[i] = mnew;
            float rs = 0.f;
#pragma unroll
            for (int j = 0; j < 4; j++) {
                s[i][j] = __expf(s[i][j] - mnew);
                rs += s[i][j];
            }
            rs = grpsum16(rs);
            lrow[i] = lrow[i] * corr[i] + rs;
        }
#pragma unroll
        for (int p = 0; p < 2; p++) {
            ull c2 = pack2(corr[2*p], corr[2*p+1]);
#pragma unroll
            for (int j = 0; j < 4; j++) mul2(o2[p][j], c2);
        }

        __syncthreads();   // O-gemm(st-1) reads of Ps / next-buf done everywhere

        // store P^T: element (s=4tx+j, t-block ty) at slot 4*(ty^tx)
#pragma unroll
        for (int j = 0; j < 4; j++) {
            *(float4*)&Ps[(4 * tx + j) * 64 + 4 * (ty ^ tx)] =
                make_float4(s[0][j], s[1][j], s[2][j], s[3][j]);
        }
        if (pf) {
            sts_T(Qb[(st + 1) & 1], tx, ty, pq);
            sts_N(Vb[(st + 1) & 1], tx, ty, pv);
        }
        __syncthreads();   // Ps + next buffers visible

        // ---- O += P x V (outer product over s) ----
#pragma unroll 1
        for (int s4 = 0; s4 < 16; s4++)
            gemm_step(o2, &Ps[(4 * s4) * 64 + 4 * (ty ^ s4)],
                           &Vcur[(4 * s4) * 64 + 4 * tx]);
    }

    // ---- normalize and write ----
    float o[4][4];
#pragma unroll
    for (int p = 0; p < 2; p++)
#pragma unroll
        for (int j = 0; j < 4; j++) unpack2(o2[p][j], o[2*p][j], o[2*p+1][j]);
#pragma unroll
    for (int i = 0; i < 4; i++) {
        float inv = 1.0f / lrow[i];
        float4 ov;
        ov.x = o[i][0] * inv; ov.y = o[i][1] * inv;
        ov.z = o[i][2] * inv; ov.w = o[i][3] * inv;
        *(float4*)(out + (rowbase + 4 * ty + i) * HH + 4 * tx) = ov;
    }
}

extern "C" void kernel_launch(void* const* d_in, const int* in_sizes, int n_in,
                              void* d_out, int out_size)
{
    const float* x  = (const float*)d_in[0];
    const float* Wk = (const float*)d_in[1];
    const float* bk = (const float*)d_in[2];
    const float* Wq = (const float*)d_in[3];
    const float* bq = (const float*)d_in[4];
    const float* Wv = (const float*)d_in[5];
    const float* bv = (const float*)d_in[6];
    float* out = (float*)d_out;

    static bool attr_done = false;
    if (!attr_done) {
        cudaFuncSetAttribute(qkv_kernel,
            cudaFuncAttributeMaxDynamicSharedMemorySize, 64 * 1024);
        cudaFuncSetAttribute(attn_kernel,
            cudaFuncAttributeMaxDynamicSharedMemorySize, 96 * 1024);
        attr_done = true;
    }

    dim3 g1(NROW / 64, 3);    // 256 row-tiles x {k,q,v}
    qkv_kernel<<<g1, 256, 64 * 1024>>>(x, Wk, bk, Wq, bq, Wv, bv);

    attn_kernel<<<256, 256, 96 * 1024>>>(out);   // descending-work CTA order
}

// round 4
// speedup vs baseline: 1.5177x; 1.5177x over previous
#include <cuda_runtime.h>
#include <math_constants.h>

#define BB 4
#define TT 4096
#define DD 1024
#define HH 64
#define NROW (BB*TT)

typedef unsigned long long ull;

// Scratch — __device__ globals per allocation rules.
__device__ float g_K[NROW*HH];
__device__ float g_Q[NROW*HH];
__device__ float g_V[NROW*HH];
__device__ float g_Oa[2*NROW*HH];   // split partial O (unnormalized)
__device__ float g_M[2*NROW];       // split partial running max
__device__ float g_L[2*NROW];       // split partial running sum

// ---- packed f32x2 helpers (ptxas never emits these from C++) ----
__device__ __forceinline__ ull pack2(float lo, float hi) {
    ull r; asm("mov.b64 %0, {%1,%2};" : "=l"(r) : "f"(lo), "f"(hi)); return r;
}
__device__ __forceinline__ void unpack2(ull v, float& lo, float& hi) {
    asm("mov.b64 {%0,%1}, %2;" : "=f"(lo), "=f"(hi) : "l"(v));
}
__device__ __forceinline__ void ffma2(ull& d, ull a, ull b) {
    asm("fma.rn.f32x2 %0, %1, %2, %0;" : "+l"(d) : "l"(a), "l"(b));
}
__device__ __forceinline__ void mul2(ull& d, ull a) {
    asm("mul.rn.f32x2 %0, %0, %1;" : "+l"(d) : "l"(a));
}

__device__ __forceinline__ float grpmax16(float v) {
#pragma unroll
    for (int m = 8; m >= 1; m >>= 1)
        v = fmaxf(v, __shfl_xor_sync(0xffffffffu, v, m));
    return v;
}
__device__ __forceinline__ float grpsum16(float v) {
#pragma unroll
    for (int m = 8; m >= 1; m >>= 1)
        v += __shfl_xor_sync(0xffffffffu, v, m);
    return v;
}

// 8 rows (4 f32x2 pairs) x 4 cols outer-product micro-kernel over 4 k-steps.
__device__ __forceinline__ void gemm_step8(ull (&acc)[4][4],
                                           const float* __restrict__ a0p,
                                           const float* __restrict__ a1p,
                                           const float* __restrict__ bp) {
#pragma unroll
    for (int kk = 0; kk < 4; kk++) {
        ulonglong2 A0 = *(const ulonglong2*)(a0p + kk * 64);
        ulonglong2 A1 = *(const ulonglong2*)(a1p + kk * 64);
        float4 bq = *(const float4*)(bp + kk * 64);
        ull b0 = pack2(bq.x, bq.x), b1 = pack2(bq.y, bq.y);
        ull b2 = pack2(bq.z, bq.z), b3 = pack2(bq.w, bq.w);
        ffma2(acc[0][0], A0.x, b0); ffma2(acc[0][1], A0.x, b1);
        ffma2(acc[0][2], A0.x, b2); ffma2(acc[0][3], A0.x, b3);
        ffma2(acc[1][0], A0.y, b0); ffma2(acc[1][1], A0.y, b1);
        ffma2(acc[1][2], A0.y, b2); ffma2(acc[1][3], A0.y, b3);
        ffma2(acc[2][0], A1.x, b0); ffma2(acc[2][1], A1.x, b1);
        ffma2(acc[2][2], A1.x, b2); ffma2(acc[2][3], A1.x, b3);
        ffma2(acc[3][0], A1.y, b0); ffma2(acc[3][1], A1.y, b1);
        ffma2(acc[3][2], A1.y, b2); ffma2(acc[3][3], A1.y, b3);
    }
}

// ---------------------------------------------------------------------------
// QKV projection: out = x @ W + b. 64x64 CTA tile, 128 threads, 8x4 micro
// (rows packed in f32x2 pairs). X chunk transposed + XOR-swizzled.
// ---------------------------------------------------------------------------
__global__ __launch_bounds__(128)
void qkv_kernel(const float* __restrict__ x,
                const float* __restrict__ Wk, const float* __restrict__ bk,
                const float* __restrict__ Wq, const float* __restrict__ bq,
                const float* __restrict__ Wv, const float* __restrict__ bv)
{
    __shared__ float Xst[64][64];   // transposed+swizzled: (k, t)
    __shared__ float Ws [64][64];   // (k, n) natural

    const float* W; const float* bias; float* out;
    if (blockIdx.y == 0)      { W = Wk; bias = bk; out = g_K; }
    else if (blockIdx.y == 1) { W = Wq; bias = bq; out = g_Q; }
    else                      { W = Wv; bias = bv; out = g_V; }

    const int tid = threadIdx.x;
    const int tx = tid & 15, ty = tid >> 4;       // ty 0..7 -> rows 8ty..8ty+7
    const int row0 = blockIdx.x * 64;

    ull acc2[4][4];
    ull zz = pack2(0.f, 0.f);
#pragma unroll
    for (int p = 0; p < 4; p++)
#pragma unroll
        for (int j = 0; j < 4; j++) acc2[p][j] = zz;

    for (int k0 = 0; k0 < DD; k0 += 64) {
        __syncthreads();
#pragma unroll
        for (int u = 0; u < 8; u++) {
            int sid = tid + 128 * u;
            int r = sid >> 4, c4 = sid & 15;
            float4 v = *(const float4*)(x + (size_t)(row0 + r) * DD + k0 + 4 * c4);
            int col = 4 * ((r >> 2) ^ c4) + (r & 3);
            Xst[4 * c4 + 0][col] = v.x;
            Xst[4 * c4 + 1][col] = v.y;
            Xst[4 * c4 + 2][col] = v.z;
            Xst[4 * c4 + 3][col] = v.w;
            float4 w = *(const float4*)(W + (size_t)(k0 + r) * HH + 4 * c4);
            *(float4*)&Ws[r][4 * c4] = w;
        }
        __syncthreads();
#pragma unroll 1
        for (int k4 = 0; k4 < 16; k4++)
            gemm_step8(acc2, &Xst[4 * k4][4 * ((2 * ty)     ^ k4)],
                             &Xst[4 * k4][4 * ((2 * ty + 1) ^ k4)],
                             &Ws [4 * k4][4 * tx]);
    }
    float4 bb = *(const float4*)(bias + 4 * tx);
    float a[8][4];
#pragma unroll
    for (int p = 0; p < 4; p++)
#pragma unroll
        for (int j = 0; j < 4; j++) unpack2(acc2[p][j], a[2*p][j], a[2*p+1][j]);
#pragma unroll
    for (int i = 0; i < 8; i++) {
        float4 o;
        o.x = a[i][0] + bb.x; o.y = a[i][1] + bb.y;
        o.z = a[i][2] + bb.z; o.w = a[i][3] + bb.w;
        *(float4*)(out + (size_t)(row0 + 8 * ty + i) * HH + 4 * tx) = o;
    }
}

// ---------------------------------------------------------------------------
// Causal flash attention, split-K (2 column-range splits per row-tile).
// fp32, f32x2 packed, 64x64 tiles, 128 threads, 8x4 micro. Each CTA emits an
// UNnormalized partial (O, m, l); combine_kernel merges the two splits.
// 512 CTAs in descending-work order -> LPT via work-stealing.
// ---------------------------------------------------------------------------
__global__ __launch_bounds__(128)
void attn_kernel()
{
    __shared__ float Kst[64][64];  // transposed+swizzled k-tile (h, t)
    __shared__ float QP [64][64];  // transposed+swizzled q-tile (h, s); reused as P^T
    __shared__ float Vs [64][64];  // natural (s, h)

    const int tid = threadIdx.x;
    const int tx = tid & 15, ty = tid >> 4;       // ty 0..7 -> rows 8ty..8ty+7
    const int bid = blockIdx.x;                   // 0..511
    const int bt    = 63 - (bid >> 3);            // descending work order
    const int b     = (bid >> 1) & 3;
    const int split = bid & 1;
    const int sp    = (bt + 1) >> 1;
    const int st_lo = split ? sp : 0;
    const int st_hi = split ? bt : sp - 1;        // split0 empty iff bt==0

    const size_t rowbase = (size_t)b * TT + (size_t)bt * 64;

    // load K row-tile (transposed + swizzled)
#pragma unroll
    for (int u = 0; u < 8; u++) {
        int sid = tid + 128 * u;
        int r = sid >> 4, c4 = sid & 15;
        float4 v = *(const float4*)(g_K + (rowbase + r) * HH + 4 * c4);
        int col = 4 * ((r >> 2) ^ c4) + (r & 3);
        Kst[4 * c4 + 0][col] = v.x;
        Kst[4 * c4 + 1][col] = v.y;
        Kst[4 * c4 + 2][col] = v.z;
        Kst[4 * c4 + 3][col] = v.w;
    }

    ull o2[4][4];
    ull zz = pack2(0.f, 0.f);
#pragma unroll
    for (int p = 0; p < 4; p++)
#pragma unroll
        for (int j = 0; j < 4; j++) o2[p][j] = zz;
    float mrow[8], lrow[8];
#pragma unroll
    for (int i = 0; i < 8; i++) { mrow[i] = -CUDART_INF_F; lrow[i] = 0.f; }

#pragma unroll 1
    for (int st = st_lo; st <= st_hi; st++) {
        const size_t colbase = (size_t)b * TT + (size_t)st * 64;
        __syncthreads();   // prev O-gemm done with QP/Vs; Kst visible first iter
#pragma unroll
        for (int u = 0; u < 8; u++) {
            int sid = tid + 128 * u;
            int r = sid >> 4, c4 = sid & 15;
            float4 v = *(const float4*)(g_Q + (colbase + r) * HH + 4 * c4);
            int col = 4 * ((r >> 2) ^ c4) + (r & 3);
            QP[4 * c4 + 0][col] = v.x;
            QP[4 * c4 + 1][col] = v.y;
            QP[4 * c4 + 2][col] = v.z;
            QP[4 * c4 + 3][col] = v.w;
            float4 w = *(const float4*)(g_V + (colbase + r) * HH + 4 * c4);
            *(float4*)&Vs[r][4 * c4] = w;
        }
        __syncthreads();

        // ---- S = k-rows x q-cols (outer product over h) ----
        ull s2[4][4];
#pragma unroll
        for (int p = 0; p < 4; p++)
#pragma unroll
            for (int j = 0; j < 4; j++) s2[p][j] = zz;
#pragma unroll 1
        for (int k4 = 0; k4 < 16; k4++)
            gemm_step8(s2, &Kst[4 * k4][4 * ((2 * ty)     ^ k4)],
                           &Kst[4 * k4][4 * ((2 * ty + 1) ^ k4)],
                           &QP [4 * k4][4 * (tx ^ k4)]);

        float s[8][4];
#pragma unroll
        for (int p = 0; p < 4; p++)
#pragma unroll
            for (int j = 0; j < 4; j++) unpack2(s2[p][j], s[2*p][j], s[2*p+1][j]);

        const float scale = 0.125f;   // 1/sqrt(64)
        if (st == bt) {
#pragma unroll
            for (int i = 0; i < 8; i++)
#pragma unroll
                for (int j = 0; j < 4; j++) {
                    int r = 8 * ty + i, c = 4 * tx + j;
                    s[i][j] = (c <= r) ? s[i][j] * scale : -1e30f;
                }
        } else {
#pragma unroll
            for (int i = 0; i < 8; i++)
#pragma unroll
                for (int j = 0; j < 4; j++) s[i][j] *= scale;
        }

        // ---- online softmax (rows reduced across the 16 tx lanes) ----
        float corr[8];
#pragma unroll
        for (int i = 0; i < 8; i++) {
            float rm = fmaxf(fmaxf(s[i][0], s[i][1]), fmaxf(s[i][2], s[i][3]));
            rm = grpmax16(rm);
            float mnew = fmaxf(mrow[i], rm);
            corr[i] = __expf(mrow[i] - mnew);   // exp(-inf)=0 on first tile
            mrow[i] = mnew;
            float rs = 0.f;
#pragma unroll
            for (int j = 0; j < 4; j++) {
                s[i][j] = __expf(s[i][j] - mnew);
                rs += s[i][j];
            }
            rs = grpsum16(rs);
            lrow[i] = lrow[i] * corr[i] + rs;
        }
#pragma unroll
        for (int p = 0; p < 4; p++) {
            ull c2 = pack2(corr[2*p], corr[2*p+1]);
#pragma unroll
            for (int j = 0; j < 4; j++) mul2(o2[p][j], c2);
        }

        __syncthreads();   // all S-gemm reads of QP done
        // ---- store P^T into QP: element (s,t) at slot (t>>2)^(s>>2) ----
#pragma unroll
        for (int j = 0; j < 4; j++) {
            int prow = 4 * tx + j;
#pragma unroll
            for (int i2 = 0; i2 < 2; i2++) {
                *(float4*)&QP[prow][4 * ((2 * ty + i2) ^ tx)] =
                    make_float4(s[4*i2+0][j], s[4*i2+1][j], s[4*i2+2][j], s[4*i2+3][j]);
            }
        }
        __syncthreads();

        // ---- O += P x V (outer product over s) ----
#pragma unroll 1
        for (int s4 = 0; s4 < 16; s4++)
            gemm_step8(o2, &QP[4 * s4][4 * ((2 * ty)     ^ s4)],
                           &QP[4 * s4][4 * ((2 * ty + 1) ^ s4)],
                           &Vs[4 * s4][4 * tx]);
    }

    // ---- write UNnormalized partial + (m, l) ----
    float o[8][4];
#pragma unroll
    for (int p = 0; p < 4; p++)
#pragma unroll
        for (int j = 0; j < 4; j++) unpack2(o2[p][j], o[2*p][j], o[2*p+1][j]);
    const size_t obase = ((size_t)split * NROW + rowbase) * HH;
#pragma unroll
    for (int i = 0; i < 8; i++) {
        *(float4*)(g_Oa + obase + (size_t)(8 * ty + i) * HH + 4 * tx) =
            make_float4(o[i][0], o[i][1], o[i][2], o[i][3]);
    }
    if (tx == 0) {
#pragma unroll
        for (int i = 0; i < 8; i++) {
            size_t r = (size_t)split * NROW + rowbase + 8 * ty + i;
            g_M[r] = mrow[i];
            g_L[r] = lrow[i];
        }
    }
}

// ---------------------------------------------------------------------------
// Merge the two split partials: out = (O0*e0 + O1*e1) / (l0*e0 + l1*e1).
// ---------------------------------------------------------------------------
__global__ __launch_bounds__(256)
void combine_kernel(float* __restrict__ out)
{
    int gid = blockIdx.x * 256 + threadIdx.x;     // 16384 rows x 16 lanes
    int r = gid >> 4, lane = gid & 15;
    float m0 = g_M[r],        m1 = g_M[NROW + r];
    float l0 = g_L[r],        l1 = g_L[NROW + r];
    float M = fmaxf(m0, m1);
    float e0 = __expf(m0 - M), e1 = __expf(m1 - M);   // exp(-inf)=0 for empty split
    float inv = 1.0f / (l0 * e0 + l1 * e1);
    float4 a = *(const float4*)(g_Oa + ((size_t)r) * HH + 4 * lane);
    float4 c = *(const float4*)(g_Oa + ((size_t)(NROW + r)) * HH + 4 * lane);
    float4 ov;
    ov.x = (a.x * e0 + c.x * e1) * inv;
    ov.y = (a.y * e0 + c.y * e1) * inv;
    ov.z = (a.z * e0 + c.z * e1) * inv;
    ov.w = (a.w * e0 + c.w * e1) * inv;
    *(float4*)(out + (size_t)r * HH + 4 * lane) = ov;
}

extern "C" void kernel_launch(void* const* d_in, const int* in_sizes, int n_in,
                              void* d_out, int out_size)
{
    const float* x  = (const float*)d_in[0];
    const float* Wk = (const float*)d_in[1];
    const float* bk = (const float*)d_in[2];
    const float* Wq = (const float*)d_in[3];
    const float* bq = (const float*)d_in[4];
    const float* Wv = (const float*)d_in[5];
    const float* bv = (const float*)d_in[6];
    float* out = (float*)d_out;

    dim3 g1(NROW / 64, 3);       // 256 row-tiles x {k,q,v}
    qkv_kernel<<<g1, 128>>>(x, Wk, bk, Wq, bq, Wv, bv);

    attn_kernel<<<512, 128>>>(); // descending-work order, 2-way split-K

    combine_kernel<<<NROW * 16 / 256, 256>>>(out);
}

// round 6
// speedup vs baseline: 1.8745x; 1.2351x over previous
#include <cuda_runtime.h>
#include <cuda_bf16.h>
#include <math_constants.h>
#include <cstdint>

#define BB 4
#define TT 4096
#define DD 1024
#define HH 64
#define NROW (BB*TT)

// Scratch — __device__ globals per allocation rules.
__device__ float g_K[NROW*HH];
__device__ float g_Q[NROW*HH];
__device__ float g_V[NROW*HH];
__device__ float g_Oa[2*NROW*HH];   // split partial O (unnormalized)
__device__ float g_M[2*NROW];       // split partial running max
__device__ float g_L[2*NROW];       // split partial running sum

// ---------------- helpers ----------------
__device__ __forceinline__ uint32_t swz(uint32_t o) { return o ^ ((o >> 3) & 0x70); }

// fp32 pair -> packed bf16 hi pair + bf16 lo pair (lo = residual)
__device__ __forceinline__ void bf_split2(float x0, float x1, uint32_t& hi, uint32_t& lo) {
    __nv_bfloat16 h0 = __float2bfloat16_rn(x0);
    __nv_bfloat16 h1 = __float2bfloat16_rn(x1);
    float r0 = x0 - __bfloat162float(h0);
    float r1 = x1 - __bfloat162float(h1);
    __nv_bfloat16 l0 = __float2bfloat16_rn(r0);
    __nv_bfloat16 l1 = __float2bfloat16_rn(r1);
    hi = (uint32_t)__bfloat16_as_ushort(h0) | ((uint32_t)__bfloat16_as_ushort(h1) << 16);
    lo = (uint32_t)__bfloat16_as_ushort(l0) | ((uint32_t)__bfloat16_as_ushort(l1) << 16);
}

// m16n8k16 row.col bf16 MMA, D accumulates in place (HMMA on sm_103).
__device__ __forceinline__ void mma16816(float (&d)[4], const uint32_t (&a)[4],
                                         const uint32_t (&b)[2]) {
    asm volatile(
        "mma.sync.aligned.m16n8k16.row.col.f32.bf16.bf16.f32 "
        "{%0,%1,%2,%3}, {%4,%5,%6,%7}, {%8,%9}, {%0,%1,%2,%3};"
        : "+f"(d[0]), "+f"(d[1]), "+f"(d[2]), "+f"(d[3])
        : "r"(a[0]), "r"(a[1]), "r"(a[2]), "r"(a[3]), "r"(b[0]), "r"(b[1]));
}

// A fragment (rows R+g / R+g+8, k-step kk) from row-major bf16 SW128 tile.
__device__ __forceinline__ void ldA(uint32_t (&a)[4], const char* s,
                                    int R, int g, int t, int kk) {
    uint32_t o0 = (uint32_t)((R + g) * 128 + kk * 32 + 4 * t);
    uint32_t o1 = o0 + 8 * 128;
    a[0] = *(const uint32_t*)(s + swz(o0));
    a[1] = *(const uint32_t*)(s + swz(o1));
    a[2] = *(const uint32_t*)(s + swz(o0 + 16));
    a[3] = *(const uint32_t*)(s + swz(o1 + 16));
}
// B fragment (n-tile j, k-step kk) from row-major bf16 SW128 tile (rows = n).
__device__ __forceinline__ void ldB(uint32_t (&b)[2], const char* s,
                                    int j, int g, int t, int kk) {
    uint32_t o = (uint32_t)((8 * j + g) * 128 + kk * 32 + 4 * t);
    b[0] = *(const uint32_t*)(s + swz(o));
    b[1] = *(const uint32_t*)(s + swz(o + 16));
}

// Convert 64x64 fp32 tile (row stride ldf floats) -> hi/lo bf16 SW128 tiles.
// 128 threads: r = tid>>1, col half = (tid&1)*32.
__device__ __forceinline__ void cvt_tile64(const float* __restrict__ g, int ldf,
                                           char* s_hi, char* s_lo, int tid) {
    int r = tid >> 1;
    int c0 = (tid & 1) * 32;
    const float* gp = g + (size_t)r * ldf + c0;
#pragma unroll
    for (int j = 0; j < 32; j += 8) {
        float4 a = *(const float4*)(gp + j);
        float4 b = *(const float4*)(gp + j + 4);
        uint4 hi, lo;
        bf_split2(a.x, a.y, hi.x, lo.x);
        bf_split2(a.z, a.w, hi.y, lo.y);
        bf_split2(b.x, b.y, hi.z, lo.z);
        bf_split2(b.z, b.w, hi.w, lo.w);
        uint32_t off = swz((uint32_t)(r * 128 + (c0 + j) * 2));
        *(uint4*)(s_hi + off) = hi;
        *(uint4*)(s_lo + off) = lo;
    }
}

// Convert 64x64 fp32 [s][h] (row stride ldf) -> TRANSPOSED hi/lo tiles T[h][s].
__device__ __forceinline__ void cvt_tileT(const float* __restrict__ g, int ldf,
                                          char* s_hi, char* s_lo, int tid) {
    int h = tid & 63;
    int s0 = (tid >> 6) * 32;
#pragma unroll
    for (int j = 0; j < 32; j += 8) {
        float v[8];
#pragma unroll
        for (int e = 0; e < 8; e++)
            v[e] = g[(size_t)(s0 + j + e) * ldf + h];
        uint4 hi, lo;
        bf_split2(v[0], v[1], hi.x, lo.x);
        bf_split2(v[2], v[3], hi.y, lo.y);
        bf_split2(v[4], v[5], hi.z, lo.z);
        bf_split2(v[6], v[7], hi.w, lo.w);
        uint32_t off = swz((uint32_t)(h * 128 + (s0 + j) * 2));
        *(uint4*)(s_hi + off) = hi;
        *(uint4*)(s_lo + off) = lo;
    }
}

// 3-chain split-bf16 accumulate: D += Ahi*Bhi + Ahi*Blo + Alo*Bhi
__device__ __forceinline__ void mma3(float (&d)[4], const uint32_t (&ah)[4],
                                     const uint32_t (&al)[4], const uint32_t (&bh)[2],
                                     const uint32_t (&bl)[2]) {
    mma16816(d, ah, bh);
    mma16816(d, ah, bl);
    mma16816(d, al, bh);
}

// ---------------------------------------------------------------------------
// QKV projection via HMMA: out = x @ W + b. 64 rows x 64 cols per CTA,
// K chunks of 64, split-bf16 3-chain. 128 threads (4 warps x 16 rows).
// ---------------------------------------------------------------------------
#define QKV_SMEM (32768 + 1024)
__global__ __launch_bounds__(128)
void qkv_kernel(const float* __restrict__ x,
                const float* __restrict__ Wk, const float* __restrict__ bk,
                const float* __restrict__ Wq, const float* __restrict__ bq,
                const float* __restrict__ Wv, const float* __restrict__ bv)
{
    extern __shared__ char dsm[];
    char* smc = (char*)(((uintptr_t)dsm + 1023) & ~(uintptr_t)1023);
    char* Xhi = smc;          char* Xlo = smc + 8192;
    char* Whi = smc + 16384;  char* Wlo = smc + 24576;

    const float* W; const float* bias; float* out;
    if (blockIdx.y == 0)      { W = Wk; bias = bk; out = g_K; }
    else if (blockIdx.y == 1) { W = Wq; bias = bq; out = g_Q; }
    else                      { W = Wv; bias = bv; out = g_V; }

    const int tid = threadIdx.x;
    const int wid = tid >> 5, lane = tid & 31;
    const int g = lane >> 2, t = lane & 3;
    const int R = 16 * wid;
    const int row0 = blockIdx.x * 64;

    float dD[8][4] = {};

#pragma unroll 1
    for (int kc = 0; kc < 16; kc++) {
        __syncthreads();
        cvt_tile64(x + (size_t)row0 * DD + kc * 64, DD, Xhi, Xlo, tid);
        cvt_tileT(W + (size_t)(kc * 64) * HH, HH, Whi, Wlo, tid);
        __syncthreads();
#pragma unroll
        for (int kk = 0; kk < 4; kk++) {
            uint32_t ah[4], al[4];
            ldA(ah, Xhi, R, g, t, kk);
            ldA(al, Xlo, R, g, t, kk);
#pragma unroll
            for (int j = 0; j < 8; j++) {
                uint32_t bh[2], bl[2];
                ldB(bh, Whi, j, g, t, kk);
                ldB(bl, Wlo, j, g, t, kk);
                mma3(dD[j], ah, al, bh, bl);
            }
        }
    }

    const int r1 = row0 + R + g, r2 = r1 + 8;
#pragma unroll
    for (int j = 0; j < 8; j++) {
        int c = 8 * j + 2 * t;
        float b0 = bias[c], b1 = bias[c + 1];
        *(float2*)(out + (size_t)r1 * HH + c) = make_float2(dD[j][0] + b0, dD[j][1] + b1);
        *(float2*)(out + (size_t)r2 * HH + c) = make_float2(dD[j][2] + b0, dD[j][3] + b1);
    }
}

// ---------------------------------------------------------------------------
// HMMA flash attention, split-bf16 (hi+lo). S[t][s] = k[t]·q[s]/8 (k @ q^T).
// CTA = 64 t-rows, 64-col s-tiles, 128 threads (4 warps x m16).
// 2-way split-K -> 512 CTAs descending by work. Emits unnormalized (O, m, l).
// P stays in registers: S-accum fragments repack directly into A fragments.
// ---------------------------------------------------------------------------
#define ATT_SMEM (49152 + 1024)
__global__ __launch_bounds__(128)
void attn_mma_kernel()
{
    extern __shared__ char dsm[];
    char* smc = (char*)(((uintptr_t)dsm + 1023) & ~(uintptr_t)1023);
    char* Khi = smc;          char* Klo = smc + 8192;
    char* Qhi = smc + 16384;  char* Qlo = smc + 24576;
    char* Vhi = smc + 32768;  char* Vlo = smc + 40960;

    const int tid = threadIdx.x;
    const int wid = tid >> 5, lane = tid & 31;
    const int g = lane >> 2, t = lane & 3;
    const int R = 16 * wid;

    const int bid   = blockIdx.x;              // 0..511
    const int bt    = 63 - (bid >> 3);         // descending work order
    const int b     = (bid >> 1) & 3;
    const int split = bid & 1;
    const int sp    = (bt + 1) >> 1;
    const int st_lo = split ? sp : 0;
    const int st_hi = split ? bt : sp - 1;

    const size_t Rg = (size_t)b * TT + (size_t)bt * 64;
    const size_t Cb = (size_t)b * TT;
    const int trow1 = bt * 64 + R + g;          // global row of c0/c1
    const int trow2 = trow1 + 8;                // global row of c2/c3

    // K tile -> hi/lo bf16 (once)
    cvt_tile64(g_K + Rg * HH, HH, Khi, Klo, tid);

    float dO[8][4] = {};
    float m1 = -CUDART_INF_F, m2 = -CUDART_INF_F, l1 = 0.f, l2 = 0.f;

#pragma unroll 1
    for (int st = st_lo; st <= st_hi; st++) {
        __syncthreads();    // previous iteration's LDS reads of Q/V done
        cvt_tile64(g_Q + (Cb + (size_t)st * 64) * HH, HH, Qhi, Qlo, tid);
        cvt_tileT(g_V + (Cb + (size_t)st * 64) * HH, HH, Vhi, Vlo, tid);
        __syncthreads();

        // ---- S = K @ Q^T (A = K rows, B = Q rows as col-major) ----
        float dS[8][4] = {};
#pragma unroll
        for (int kk = 0; kk < 4; kk++) {
            uint32_t ah[4], al[4];
            ldA(ah, Khi, R, g, t, kk);
            ldA(al, Klo, R, g, t, kk);
#pragma unroll
            for (int j = 0; j < 8; j++) {
                uint32_t bh[2], bl[2];
                ldB(bh, Qhi, j, g, t, kk);
                ldB(bl, Qlo, j, g, t, kk);
                mma3(dS[j], ah, al, bh, bl);
            }
        }

        // ---- scale + causal mask ----
        if (st == bt) {
#pragma unroll
            for (int j = 0; j < 8; j++) {
                int c0 = st * 64 + 8 * j + 2 * t;
                dS[j][0] = (c0     <= trow1) ? dS[j][0] * 0.125f : -1e30f;
                dS[j][1] = (c0 + 1 <= trow1) ? dS[j][1] * 0.125f : -1e30f;
                dS[j][2] = (c0     <= trow2) ? dS[j][2] * 0.125f : -1e30f;
                dS[j][3] = (c0 + 1 <= trow2) ? dS[j][3] * 0.125f : -1e30f;
            }
        } else {
#pragma unroll
            for (int j = 0; j < 8; j++) {
                dS[j][0] *= 0.125f; dS[j][1] *= 0.125f;
                dS[j][2] *= 0.125f; dS[j][3] *= 0.125f;
            }
        }

        // ---- online softmax (rows spread across the 4 quad threads) ----
        float rmax1 = -CUDART_INF_F, rmax2 = -CUDART_INF_F;
#pragma unroll
        for (int j = 0; j < 8; j++) {
            rmax1 = fmaxf(rmax1, fmaxf(dS[j][0], dS[j][1]));
            rmax2 = fmaxf(rmax2, fmaxf(dS[j][2], dS[j][3]));
        }
        rmax1 = fmaxf(rmax1, __shfl_xor_sync(0xffffffffu, rmax1, 1));
        rmax1 = fmaxf(rmax1, __shfl_xor_sync(0xffffffffu, rmax1, 2));
        rmax2 = fmaxf(rmax2, __shfl_xor_sync(0xffffffffu, rmax2, 1));
        rmax2 = fmaxf(rmax2, __shfl_xor_sync(0xffffffffu, rmax2, 2));

        float mn1 = fmaxf(m1, rmax1), mn2 = fmaxf(m2, rmax2);
        float corr1 = __expf(m1 - mn1), corr2 = __expf(m2 - mn2);
        m1 = mn1; m2 = mn2;

        float sum1 = 0.f, sum2 = 0.f;
#pragma unroll
        for (int j = 0; j < 8; j++) {
            dS[j][0] = __expf(dS[j][0] - mn1);
            dS[j][1] = __expf(dS[j][1] - mn1);
            dS[j][2] = __expf(dS[j][2] - mn2);
            dS[j][3] = __expf(dS[j][3] - mn2);
            sum1 += dS[j][0] + dS[j][1];
            sum2 += dS[j][2] + dS[j][3];
        }
        sum1 += __shfl_xor_sync(0xffffffffu, sum1, 1);
        sum1 += __shfl_xor_sync(0xffffffffu, sum1, 2);
        sum2 += __shfl_xor_sync(0xffffffffu, sum2, 1);
        sum2 += __shfl_xor_sync(0xffffffffu, sum2, 2);
        l1 = l1 * corr1 + sum1;
        l2 = l2 * corr2 + sum2;
#pragma unroll
        for (int j = 0; j < 8; j++) {
            dO[j][0] *= corr1; dO[j][1] *= corr1;
            dO[j][2] *= corr2; dO[j][3] *= corr2;
        }

        // ---- O += P @ V : P fragments built in registers from dS ----
#pragma unroll
        for (int ss = 0; ss < 4; ss++) {
            uint32_t pah[4], pal[4];
            bf_split2(dS[2*ss][0],   dS[2*ss][1],   pah[0], pal[0]);
            bf_split2(dS[2*ss][2],   dS[2*ss][3],   pah[1], pal[1]);
            bf_split2(dS[2*ss+1][0], dS[2*ss+1][1], pah[2], pal[2]);
            bf_split2(dS[2*ss+1][2], dS[2*ss+1][3], pah[3], pal[3]);
#pragma unroll
            for (int j = 0; j < 8; j++) {
                uint32_t bh[2], bl[2];
                ldB(bh, Vhi, j, g, t, ss);
                ldB(bl, Vlo, j, g, t, ss);
                mma3(dO[j], pah, pal, bh, bl);
            }
        }
    }

    // ---- write unnormalized partial + (m, l) ----
    const size_t orow1 = (size_t)split * NROW + Rg + R + g;
    const size_t orow2 = orow1 + 8;
#pragma unroll
    for (int j = 0; j < 8; j++) {
        int c = 8 * j + 2 * t;
        *(float2*)(g_Oa + orow1 * HH + c) = make_float2(dO[j][0], dO[j][1]);
        *(float2*)(g_Oa + orow2 * HH + c) = make_float2(dO[j][2], dO[j][3]);
    }
    if (t == 0) {
        g_M[orow1] = m1; g_L[orow1] = l1;
        g_M[orow2] = m2; g_L[orow2] = l2;
    }
}

// ---------------------------------------------------------------------------
// Merge the two split partials: out = (O0*e0 + O1*e1) / (l0*e0 + l1*e1).
// ---------------------------------------------------------------------------
__global__ __launch_bounds__(256)
void combine_kernel(float* __restrict__ out)
{
    int gid = blockIdx.x * 256 + threadIdx.x;
    int r = gid >> 4, lane = gid & 15;
    float m0 = g_M[r],        mm1 = g_M[NROW + r];
    float l0 = g_L[r],        ll1 = g_L[NROW + r];
    float M = fmaxf(m0, mm1);
    float e0 = __expf(m0 - M), e1 = __expf(mm1 - M);
    float inv = 1.0f / (l0 * e0 + ll1 * e1);
    float4 a = *(const float4*)(g_Oa + ((size_t)r) * HH + 4 * lane);
    float4 c = *(const float4*)(g_Oa + ((size_t)(NROW + r)) * HH + 4 * lane);
    float4 ov;
    ov.x = (a.x * e0 + c.x * e1) * inv;
    ov.y = (a.y * e0 + c.y * e1) * inv;
    ov.z = (a.z * e0 + c.z * e1) * inv;
    ov.w = (a.w * e0 + c.w * e1) * inv;
    *(float4*)(out + (size_t)r * HH + 4 * lane) = ov;
}

extern "C" void kernel_launch(void* const* d_in, const int* in_sizes, int n_in,
                              void* d_out, int out_size)
{
    const float* x  = (const float*)d_in[0];
    const float* Wk = (const float*)d_in[1];
    const float* bk = (const float*)d_in[2];
    const float* Wq = (const float*)d_in[3];
    const float* bq = (const float*)d_in[4];
    const float* Wv = (const float*)d_in[5];
    const float* bv = (const float*)d_in[6];
    float* out = (float*)d_out;

    static bool attr_done = false;
    if (!attr_done) {
        cudaFuncSetAttribute(attn_mma_kernel,
            cudaFuncAttributeMaxDynamicSharedMemorySize, ATT_SMEM);
        cudaFuncSetAttribute(qkv_kernel,
            cudaFuncAttributeMaxDynamicSharedMemorySize, QKV_SMEM);
        attr_done = true;
    }

    dim3 g1(NROW / 64, 3);
    qkv_kernel<<<g1, 128, QKV_SMEM>>>(x, Wk, bk, Wq, bq, Wv, bv);

    attn_mma_kernel<<<512, 128, ATT_SMEM>>>();

    combine_kernel<<<NROW * 16 / 256, 256>>>(out);
}

// round 7
// speedup vs baseline: 2.3151x; 1.2350x over previous
#include <cuda_runtime.h>
#include <cuda_bf16.h>
#include <math_constants.h>
#include <cstdint>

#define BB 4
#define TT 4096
#define DD 1024
#define HH 64
#define NROW (BB*TT)

// Scratch — __device__ globals per allocation rules.
__device__ unsigned short g_Xhi[NROW*DD];     // x split-bf16 (row-major)
__device__ unsigned short g_Xlo[NROW*DD];
__device__ unsigned short g_Wthi[3*HH*DD];    // W^T split-bf16: [m][n][k]
__device__ unsigned short g_Wtlo[3*HH*DD];
__device__ unsigned short g_Khi[NROW*HH];     // k,q split-bf16 (row-major)
__device__ unsigned short g_Klo[NROW*HH];
__device__ unsigned short g_Qhi[NROW*HH];
__device__ unsigned short g_Qlo[NROW*HH];
__device__ unsigned short g_Vthi[BB*HH*TT];   // v split-bf16 TRANSPOSED: [b][h][t]
__device__ unsigned short g_Vtlo[BB*HH*TT];
__device__ float g_Oa[2*NROW*HH];             // split partial O (unnormalized)
__device__ float g_M[2*NROW];
__device__ float g_L[2*NROW];

// ---------------- helpers ----------------
__device__ __forceinline__ uint32_t swz(uint32_t o) { return o ^ ((o >> 3) & 0x70); }

__device__ __forceinline__ void bf_split2(float x0, float x1, uint32_t& hi, uint32_t& lo) {
    __nv_bfloat16 h0 = __float2bfloat16_rn(x0);
    __nv_bfloat16 h1 = __float2bfloat16_rn(x1);
    float r0 = x0 - __bfloat162float(h0);
    float r1 = x1 - __bfloat162float(h1);
    __nv_bfloat16 l0 = __float2bfloat16_rn(r0);
    __nv_bfloat16 l1 = __float2bfloat16_rn(r1);
    hi = (uint32_t)__bfloat16_as_ushort(h0) | ((uint32_t)__bfloat16_as_ushort(h1) << 16);
    lo = (uint32_t)__bfloat16_as_ushort(l0) | ((uint32_t)__bfloat16_as_ushort(l1) << 16);
}

__device__ __forceinline__ void mma16816(float (&d)[4], const uint32_t (&a)[4],
                                         const uint32_t (&b)[2]) {
    asm volatile(
        "mma.sync.aligned.m16n8k16.row.col.f32.bf16.bf16.f32 "
        "{%0,%1,%2,%3}, {%4,%5,%6,%7}, {%8,%9}, {%0,%1,%2,%3};"
        : "+f"(d[0]), "+f"(d[1]), "+f"(d[2]), "+f"(d[3])
        : "r"(a[0]), "r"(a[1]), "r"(a[2]), "r"(a[3]), "r"(b[0]), "r"(b[1]));
}

__device__ __forceinline__ void ldA(uint32_t (&a)[4], const char* s,
                                    int R, int g, int t, int kk) {
    uint32_t o0 = (uint32_t)((R + g) * 128 + kk * 32 + 4 * t);
    uint32_t o1 = o0 + 8 * 128;
    a[0] = *(const uint32_t*)(s + swz(o0));
    a[1] = *(const uint32_t*)(s + swz(o1));
    a[2] = *(const uint32_t*)(s + swz(o0 + 16));
    a[3] = *(const uint32_t*)(s + swz(o1 + 16));
}
__device__ __forceinline__ void ldB(uint32_t (&b)[2], const char* s,
                                    int j, int g, int t, int kk) {
    uint32_t o = (uint32_t)((8 * j + g) * 128 + kk * 32 + 4 * t);
    b[0] = *(const uint32_t*)(s + swz(o));
    b[1] = *(const uint32_t*)(s + swz(o + 16));
}
__device__ __forceinline__ void mma3(float (&d)[4], const uint32_t (&ah)[4],
                                     const uint32_t (&al)[4], const uint32_t (&bh)[2],
                                     const uint32_t (&bl)[2]) {
    mma16816(d, ah, bh);
    mma16816(d, ah, bl);
    mma16816(d, al, bh);
}

// Load a 64x64 bf16 tile (row = 128B contiguous in gmem, row stride lds ushorts)
// into SW128-swizzled smem. 128 threads: r = tid>>1, half = tid&1.
__device__ __forceinline__ void ldg_tile_bf(const unsigned short* __restrict__ g,
                                            int lds, char* s, int tid) {
    int r = tid >> 1, half = tid & 1;
    const char* gp = (const char*)(g + (size_t)r * lds + half * 32);
#pragma unroll
    for (int i = 0; i < 4; i++) {
        uint4 v = *(const uint4*)(gp + 16 * i);
        *(uint4*)(s + swz((uint32_t)(r * 128 + half * 64 + 16 * i))) = v;
    }
}

// ---------------------------------------------------------------------------
// cvt_x: x fp32 -> global bf16 hi/lo. 8 elems/thread, fully coalesced.
// ---------------------------------------------------------------------------
__global__ __launch_bounds__(256)
void cvt_x_kernel(const float* __restrict__ x)
{
    size_t e = ((size_t)blockIdx.x * 256 + threadIdx.x) * 8;
    float4 a = *(const float4*)(x + e);
    float4 b = *(const float4*)(x + e + 4);
    uint4 hi, lo;
    bf_split2(a.x, a.y, hi.x, lo.x);
    bf_split2(a.z, a.w, hi.y, lo.y);
    bf_split2(b.x, b.y, hi.z, lo.z);
    bf_split2(b.z, b.w, hi.w, lo.w);
    *(uint4*)(g_Xhi + e) = hi;
    *(uint4*)(g_Xlo + e) = lo;
}

// ---------------------------------------------------------------------------
// cvt_w: W[k][n] fp32 -> Wt[m][n][k] bf16 hi/lo. grid 24 x 128.
// ---------------------------------------------------------------------------
__global__ __launch_bounds__(128)
void cvt_w_kernel(const float* __restrict__ Wk, const float* __restrict__ Wq,
                  const float* __restrict__ Wv)
{
    const int m = blockIdx.x >> 3;
    const int n = (blockIdx.x & 7) * 8 + (threadIdx.x >> 4);
    const int k0 = (threadIdx.x & 15) * 64;
    const float* W = (m == 0) ? Wk : (m == 1) ? Wq : Wv;
    const size_t base = (size_t)m * HH * DD + (size_t)n * DD;
#pragma unroll 4
    for (int kk = 0; kk < 32; kk++) {
        int k = k0 + 2 * kk;
        float f0 = W[(size_t)k * HH + n];
        float f1 = W[(size_t)(k + 1) * HH + n];
        uint32_t hi, lo;
        bf_split2(f0, f1, hi, lo);
        *(uint32_t*)(g_Wthi + base + k) = hi;
        *(uint32_t*)(g_Wtlo + base + k) = lo;
    }
}

// ---------------------------------------------------------------------------
// QKV via HMMA from preconverted bf16: out = x @ W + b, split directly to
// bf16 hi/lo (K/Q row-major, V transposed via smem staging). 64x64 tile,
// 128 threads, K chunks of 64, 3-chain split-bf16.
// ---------------------------------------------------------------------------
__global__ __launch_bounds__(128)
void qkv_kernel(const float* __restrict__ bk, const float* __restrict__ bq,
                const float* __restrict__ bv)
{
    __shared__ __align__(16) char sq[32768];
    char* Xhi = sq;          char* Xlo = sq + 8192;
    char* Whi = sq + 16384;  char* Wlo = sq + 24576;

    const int m = blockIdx.y;
    const float* bias = (m == 0) ? bk : (m == 1) ? bq : bv;

    const int tid = threadIdx.x;
    const int wid = tid >> 5, lane = tid & 31;
    const int g = lane >> 2, t = lane & 3;
    const int R = 16 * wid;
    const int row0 = blockIdx.x * 64;
    const size_t wbase = (size_t)m * HH * DD;

    float dD[8][4] = {};

#pragma unroll 1
    for (int kc = 0; kc < 16; kc++) {
        __syncthreads();
        ldg_tile_bf(g_Xhi + (size_t)row0 * DD + kc * 64, DD, Xhi, tid);
        ldg_tile_bf(g_Xlo + (size_t)row0 * DD + kc * 64, DD, Xlo, tid);
        ldg_tile_bf(g_Wthi + wbase + kc * 64, DD, Whi, tid);
        ldg_tile_bf(g_Wtlo + wbase + kc * 64, DD, Wlo, tid);
        __syncthreads();
#pragma unroll
        for (int kk = 0; kk < 4; kk++) {
            uint32_t ah[4], al[4];
            ldA(ah, Xhi, R, g, t, kk);
            ldA(al, Xlo, R, g, t, kk);
#pragma unroll
            for (int j = 0; j < 8; j++) {
                uint32_t bh[2], bl[2];
                ldB(bh, Whi, j, g, t, kk);
                ldB(bl, Wlo, j, g, t, kk);
                mma3(dD[j], ah, al, bh, bl);
            }
        }
    }

    const int r1 = R + g, r2 = r1 + 8;   // rows within tile
    if (m < 2) {
        unsigned short* ohi = (m == 0) ? g_Khi : g_Qhi;
        unsigned short* olo = (m == 0) ? g_Klo : g_Qlo;
#pragma unroll
        for (int j = 0; j < 8; j++) {
            int c = 8 * j + 2 * t;
            float b0 = bias[c], b1 = bias[c + 1];
            uint32_t hi, lo;
            bf_split2(dD[j][0] + b0, dD[j][1] + b1, hi, lo);
            *(uint32_t*)(ohi + (size_t)(row0 + r1) * HH + c) = hi;
            *(uint32_t*)(olo + (size_t)(row0 + r1) * HH + c) = lo;
            bf_split2(dD[j][2] + b0, dD[j][3] + b1, hi, lo);
            *(uint32_t*)(ohi + (size_t)(row0 + r2) * HH + c) = hi;
            *(uint32_t*)(olo + (size_t)(row0 + r2) * HH + c) = lo;
        }
    } else {
        // stage fp32 v-tile in smem (reuse X buffers: 16KB), then transpose-split
        float* S = (float*)sq;
        __syncthreads();
#pragma unroll
        for (int j = 0; j < 8; j++) {
            int c = 8 * j + 2 * t;
            float b0 = bias[c], b1 = bias[c + 1];
            S[r1 * 64 + c] = dD[j][0] + b0; S[r1 * 64 + c + 1] = dD[j][1] + b1;
            S[r2 * 64 + c] = dD[j][2] + b0; S[r2 * 64 + c + 1] = dD[j][3] + b1;
        }
        __syncthreads();
        const int b    = row0 >> 12;          // row0 / TT
        const int tloc = row0 & (TT - 1);
        const int h  = tid & 63;
        const int s0 = (tid >> 6) * 32;
        const size_t obase = (size_t)b * HH * TT + (size_t)h * TT + tloc + s0;
#pragma unroll
        for (int jj = 0; jj < 32; jj += 8) {
            uint4 hi, lo;
            bf_split2(S[(s0 + jj + 0) * 64 + h], S[(s0 + jj + 1) * 64 + h], hi.x, lo.x);
            bf_split2(S[(s0 + jj + 2) * 64 + h], S[(s0 + jj + 3) * 64 + h], hi.y, lo.y);
            bf_split2(S[(s0 + jj + 4) * 64 + h], S[(s0 + jj + 5) * 64 + h], hi.z, lo.z);
            bf_split2(S[(s0 + jj + 6) * 64 + h], S[(s0 + jj + 7) * 64 + h], hi.w, lo.w);
            *(uint4*)(g_Vthi + obase + jj) = hi;
            *(uint4*)(g_Vtlo + obase + jj) = lo;
        }
    }
}

// ---------------------------------------------------------------------------
// HMMA flash attention from preconverted bf16. S[t][s] = k[t]·q[s]/8.
// CTA = 64 t-rows, 64-col s-tiles, 128 threads. K fragments hoisted.
// 2-way split-K -> 512 CTAs descending by work. Emits unnormalized (O, m, l).
// ---------------------------------------------------------------------------
__global__ __launch_bounds__(128)
void attn_mma_kernel()
{
    __shared__ __align__(16) char sa[49152];
    char* Khi = sa;          char* Klo = sa + 8192;
    char* Qhi = sa + 16384;  char* Qlo = sa + 24576;
    char* Vhi = sa + 32768;  char* Vlo = sa + 40960;

    const int tid = threadIdx.x;
    const int wid = tid >> 5, lane = tid & 31;
    const int g = lane >> 2, t = lane & 3;
    const int R = 16 * wid;

    const int bid   = blockIdx.x;              // 0..511
    const int bt    = 63 - (bid >> 3);         // descending work order
    const int b     = (bid >> 1) & 3;
    const int split = bid & 1;
    const int sp    = (bt + 1) >> 1;
    const int st_lo = split ? sp : 0;
    const int st_hi = split ? bt : sp - 1;

    const size_t Rg = (size_t)b * TT + (size_t)bt * 64;
    const size_t vb = (size_t)b * HH * TT;
    const int trow1 = bt * 64 + R + g;
    const int trow2 = trow1 + 8;

    // K tile (bf16 hi/lo) -> smem, then hoist K fragments to registers
    ldg_tile_bf(g_Khi + Rg * HH, HH, Khi, tid);
    ldg_tile_bf(g_Klo + Rg * HH, HH, Klo, tid);
    __syncthreads();
    uint32_t kfh[4][4], kfl[4][4];
#pragma unroll
    for (int kk = 0; kk < 4; kk++) {
        ldA(kfh[kk], Khi, R, g, t, kk);
        ldA(kfl[kk], Klo, R, g, t, kk);
    }

    float dO[8][4] = {};
    float m1 = -CUDART_INF_F, m2 = -CUDART_INF_F, l1 = 0.f, l2 = 0.f;

#pragma unroll 1
    for (int st = st_lo; st <= st_hi; st++) {
        __syncthreads();    // previous iteration's LDS of Q/V done
        ldg_tile_bf(g_Qhi + ((size_t)b * TT + (size_t)st * 64) * HH, HH, Qhi, tid);
        ldg_tile_bf(g_Qlo + ((size_t)b * TT + (size_t)st * 64) * HH, HH, Qlo, tid);
        ldg_tile_bf(g_Vthi + vb + st * 64, TT, Vhi, tid);
        ldg_tile_bf(g_Vtlo + vb + st * 64, TT, Vlo, tid);
        __syncthreads();

        // ---- S = K @ Q^T ----
        float dS[8][4] = {};
#pragma unroll
        for (int kk = 0; kk < 4; kk++) {
#pragma unroll
            for (int j = 0; j < 8; j++) {
                uint32_t bh[2], bl[2];
                ldB(bh, Qhi, j, g, t, kk);
                ldB(bl, Qlo, j, g, t, kk);
                mma3(dS[j], kfh[kk], kfl[kk], bh, bl);
            }
        }

        // ---- scale + causal mask ----
        if (st == bt) {
#pragma unroll
            for (int j = 0; j < 8; j++) {
                int c0 = st * 64 + 8 * j + 2 * t;
                dS[j][0] = (c0     <= trow1) ? dS[j][0] * 0.125f : -1e30f;
                dS[j][1] = (c0 + 1 <= trow1) ? dS[j][1] * 0.125f : -1e30f;
                dS[j][2] = (c0     <= trow2) ? dS[j][2] * 0.125f : -1e30f;
                dS[j][3] = (c0 + 1 <= trow2) ? dS[j][3] * 0.125f : -1e30f;
            }
        } else {
#pragma unroll
            for (int j = 0; j < 8; j++) {
                dS[j][0] *= 0.125f; dS[j][1] *= 0.125f;
                dS[j][2] *= 0.125f; dS[j][3] *= 0.125f;
            }
        }

        // ---- online softmax ----
        float rmax1 = -CUDART_INF_F, rmax2 = -CUDART_INF_F;
#pragma unroll
        for (int j = 0; j < 8; j++) {
            rmax1 = fmaxf(rmax1, fmaxf(dS[j][0], dS[j][1]));
            rmax2 = fmaxf(rmax2, fmaxf(dS[j][2], dS[j][3]));
        }
        rmax1 = fmaxf(rmax1, __shfl_xor_sync(0xffffffffu, rmax1, 1));
        rmax1 = fmaxf(rmax1, __shfl_xor_sync(0xffffffffu, rmax1, 2));
        rmax2 = fmaxf(rmax2, __shfl_xor_sync(0xffffffffu, rmax2, 1));
        rmax2 = fmaxf(rmax2, __shfl_xor_sync(0xffffffffu, rmax2, 2));

        float mn1 = fmaxf(m1, rmax1), mn2 = fmaxf(m2, rmax2);
        float corr1 = __expf(m1 - mn1), corr2 = __expf(m2 - mn2);
        m1 = mn1; m2 = mn2;

        float sum1 = 0.f, sum2 = 0.f;
#pragma unroll
        for (int j = 0; j < 8; j++) {
            dS[j][0] = __expf(dS[j][0] - mn1);
            dS[j][1] = __expf(dS[j][1] - mn1);
            dS[j][2] = __expf(dS[j][2] - mn2);
            dS[j][3] = __expf(dS[j][3] - mn2);
            sum1 += dS[j][0] + dS[j][1];
            sum2 += dS[j][2] + dS[j][3];
        }
        sum1 += __shfl_xor_sync(0xffffffffu, sum1, 1);
        sum1 += __shfl_xor_sync(0xffffffffu, sum1, 2);
        sum2 += __shfl_xor_sync(0xffffffffu, sum2, 1);
        sum2 += __shfl_xor_sync(0xffffffffu, sum2, 2);
        l1 = l1 * corr1 + sum1;
        l2 = l2 * corr2 + sum2;
#pragma unroll
        for (int j = 0; j < 8; j++) {
            dO[j][0] *= corr1; dO[j][1] *= corr1;
            dO[j][2] *= corr2; dO[j][3] *= corr2;
        }

        // ---- O += P @ V (P fragments repacked in registers) ----
#pragma unroll
        for (int ss = 0; ss < 4; ss++) {
            uint32_t pah[4], pal[4];
            bf_split2(dS[2*ss][0],   dS[2*ss][1],   pah[0], pal[0]);
            bf_split2(dS[2*ss][2],   dS[2*ss][3],   pah[1], pal[1]);
            bf_split2(dS[2*ss+1][0], dS[2*ss+1][1], pah[2], pal[2]);
            bf_split2(dS[2*ss+1][2], dS[2*ss+1][3], pah[3], pal[3]);
#pragma unroll
            for (int j = 0; j < 8; j++) {
                uint32_t bh[2], bl[2];
                ldB(bh, Vhi, j, g, t, ss);
                ldB(bl, Vlo, j, g, t, ss);
                mma3(dO[j], pah, pal, bh, bl);
            }
        }
    }

    // ---- write unnormalized partial + (m, l) ----
    const size_t orow1 = (size_t)split * NROW + Rg + R + g;
    const size_t orow2 = orow1 + 8;
#pragma unroll
    for (int j = 0; j < 8; j++) {
        int c = 8 * j + 2 * t;
        *(float2*)(g_Oa + orow1 * HH + c) = make_float2(dO[j][0], dO[j][1]);
        *(float2*)(g_Oa + orow2 * HH + c) = make_float2(dO[j][2], dO[j][3]);
    }
    if (t == 0) {
        g_M[orow1] = m1; g_L[orow1] = l1;
        g_M[orow2] = m2; g_L[orow2] = l2;
    }
}

// ---------------------------------------------------------------------------
// Merge the two split partials.
// ---------------------------------------------------------------------------
__global__ __launch_bounds__(256)
void combine_kernel(float* __restrict__ out)
{
    int gid = blockIdx.x * 256 + threadIdx.x;
    int r = gid >> 4, lane = gid & 15;
    float m0 = g_M[r],  mm1 = g_M[NROW + r];
    float l0 = g_L[r],  ll1 = g_L[NROW + r];
    float M = fmaxf(m0, mm1);
    float e0 = __expf(m0 - M), e1 = __expf(mm1 - M);
    float inv = 1.0f / (l0 * e0 + ll1 * e1);
    float4 a = *(const float4*)(g_Oa + ((size_t)r) * HH + 4 * lane);
    float4 c = *(const float4*)(g_Oa + ((size_t)(NROW + r)) * HH + 4 * lane);
    float4 ov;
    ov.x = (a.x * e0 + c.x * e1) * inv;
    ov.y = (a.y * e0 + c.y * e1) * inv;
    ov.z = (a.z * e0 + c.z * e1) * inv;
    ov.w = (a.w * e0 + c.w * e1) * inv;
    *(float4*)(out + (size_t)r * HH + 4 * lane) = ov;
}

extern "C" void kernel_launch(void* const* d_in, const int* in_sizes, int n_in,
                              void* d_out, int out_size)
{
    const float* x  = (const float*)d_in[0];
    const float* Wk = (const float*)d_in[1];
    const float* bk = (const float*)d_in[2];
    const float* Wq = (const float*)d_in[3];
    const float* bq = (const float*)d_in[4];
    const float* Wv = (const float*)d_in[5];
    const float* bv = (const float*)d_in[6];
    float* out = (float*)d_out;

    cvt_x_kernel<<<NROW * DD / (256 * 8), 256>>>(x);
    cvt_w_kernel<<<24, 128>>>(Wk, Wq, Wv);

    dim3 g1(NROW / 64, 3);
    qkv_kernel<<<g1, 128>>>(bk, bq, bv);

    attn_mma_kernel<<<512, 128>>>();

    combine_kernel<<<NROW * 16 / 256, 256>>>(out);
}

// round 8
// speedup vs baseline: 2.6449x; 1.1425x over previous
#include <cuda_runtime.h>
#include <cuda_bf16.h>
#include <math_constants.h>
#include <cstdint>

#define BB 4
#define TT 4096
#define DD 1024
#define HH 64
#define NROW (BB*TT)

// Scratch — __device__ globals per allocation rules.
__device__ unsigned short g_Wthi[3*HH*DD];    // W^T split-bf16: [m][n][k] (contig n'=m*64+n)
__device__ unsigned short g_Wtlo[3*HH*DD];
__device__ unsigned short g_Khi[NROW*HH];     // k,q split-bf16 (row-major)
__device__ unsigned short g_Klo[NROW*HH];
__device__ unsigned short g_Qhi[NROW*HH];
__device__ unsigned short g_Qlo[NROW*HH];
__device__ unsigned short g_Vthi[BB*HH*TT];   // v split-bf16 TRANSPOSED: [b][h][t]
__device__ unsigned short g_Vtlo[BB*HH*TT];
__device__ float g_Oa[2*NROW*HH];             // split partial O (unnormalized)
__device__ float g_M[2*NROW];
__device__ float g_L[2*NROW];

// ---------------- helpers ----------------
__device__ __forceinline__ uint32_t swz(uint32_t o) { return o ^ ((o >> 3) & 0x70); }

__device__ __forceinline__ uint32_t smem_u32(const void* p) {
    uint32_t a;
    asm("{ .reg .u64 t; cvta.to.shared.u64 t, %1; cvt.u32.u64 %0, t; }"
        : "=r"(a) : "l"(p));
    return a;
}

__device__ __forceinline__ void bf_split2(float x0, float x1, uint32_t& hi, uint32_t& lo) {
    __nv_bfloat16 h0 = __float2bfloat16_rn(x0);
    __nv_bfloat16 h1 = __float2bfloat16_rn(x1);
    float r0 = x0 - __bfloat162float(h0);
    float r1 = x1 - __bfloat162float(h1);
    __nv_bfloat16 l0 = __float2bfloat16_rn(r0);
    __nv_bfloat16 l1 = __float2bfloat16_rn(r1);
    hi = (uint32_t)__bfloat16_as_ushort(h0) | ((uint32_t)__bfloat16_as_ushort(h1) << 16);
    lo = (uint32_t)__bfloat16_as_ushort(l0) | ((uint32_t)__bfloat16_as_ushort(l1) << 16);
}

__device__ __forceinline__ void mma16816(float (&d)[4], const uint32_t (&a)[4],
                                         const uint32_t (&b)[2]) {
    asm volatile(
        "mma.sync.aligned.m16n8k16.row.col.f32.bf16.bf16.f32 "
        "{%0,%1,%2,%3}, {%4,%5,%6,%7}, {%8,%9}, {%0,%1,%2,%3};"
        : "+f"(d[0]), "+f"(d[1]), "+f"(d[2]), "+f"(d[3])
        : "r"(a[0]), "r"(a[1]), "r"(a[2]), "r"(a[3]), "r"(b[0]), "r"(b[1]));
}
__device__ __forceinline__ void mma3(float (&d)[4], const uint32_t (&ah)[4],
                                     const uint32_t (&al)[4], const uint32_t (&bh)[2],
                                     const uint32_t (&bl)[2]) {
    mma16816(d, ah, bh);
    mma16816(d, ah, bl);
    mma16816(d, al, bh);
}

__device__ __forceinline__ void ldsm4(uint32_t (&r)[4], uint32_t saddr) {
    asm volatile("ldmatrix.sync.aligned.m8n8.x4.shared.b16 {%0,%1,%2,%3}, [%4];"
        : "=r"(r[0]), "=r"(r[1]), "=r"(r[2]), "=r"(r[3]) : "r"(saddr));
}
// B fragments for n-tiles j and j+1, k-step kk, from row-major [n][k] SW128 tile.
__device__ __forceinline__ void ldB4(uint32_t (&r)[4], uint32_t base, int j, int kk) {
    int lane = threadIdx.x & 31;
    int rsel = lane & 7, sel = lane >> 3;
    uint32_t byte = (uint32_t)((8 * (j + (sel >> 1)) + rsel) * 128 + kk * 32 + (sel & 1) * 16);
    ldsm4(r, base + swz(byte));
}
// A fragments (rows R..R+15, k-step kk) from row-major SW128 tile.
__device__ __forceinline__ void ldA4(uint32_t (&r)[4], uint32_t base, int R, int kk) {
    int lane = threadIdx.x & 31;
    int rsel = lane & 7, sel = lane >> 3;
    uint32_t byte = (uint32_t)((R + (sel & 1) * 8 + rsel) * 128 + kk * 32 + (sel >> 1) * 16);
    ldsm4(r, base + swz(byte));
}
// scalar A load (used once for K hoist)
__device__ __forceinline__ void ldA(uint32_t (&a)[4], const char* s,
                                    int R, int g, int t, int kk) {
    uint32_t o0 = (uint32_t)((R + g) * 128 + kk * 32 + 4 * t);
    uint32_t o1 = o0 + 8 * 128;
    a[0] = *(const uint32_t*)(s + swz(o0));
    a[1] = *(const uint32_t*)(s + swz(o1));
    a[2] = *(const uint32_t*)(s + swz(o0 + 16));
    a[3] = *(const uint32_t*)(s + swz(o1 + 16));
}

// Load a 64x64 bf16 tile (row stride lds ushorts) into SW128 smem. 128 threads.
__device__ __forceinline__ void ldg_tile_bf(const unsigned short* __restrict__ g,
                                            int lds, char* s, int tid) {
    int r = tid >> 1, half = tid & 1;
    const char* gp = (const char*)(g + (size_t)r * lds + half * 32);
#pragma unroll
    for (int i = 0; i < 4; i++) {
        uint4 v = *(const uint4*)(gp + 16 * i);
        *(uint4*)(s + swz((uint32_t)(r * 128 + half * 64 + 16 * i))) = v;
    }
}

// ---------------------------------------------------------------------------
// cvt_w: W[k][n] fp32 -> Wt[m][n][k] bf16 hi/lo. grid 24 x 128.
// ---------------------------------------------------------------------------
__global__ __launch_bounds__(128)
void cvt_w_kernel(const float* __restrict__ Wk, const float* __restrict__ Wq,
                  const float* __restrict__ Wv)
{
    const int m = blockIdx.x >> 3;
    const int n = (blockIdx.x & 7) * 8 + (threadIdx.x >> 4);
    const int k0 = (threadIdx.x & 15) * 64;
    const float* W = (m == 0) ? Wk : (m == 1) ? Wq : Wv;
    const size_t base = (size_t)m * HH * DD + (size_t)n * DD;
#pragma unroll 4
    for (int kk = 0; kk < 32; kk++) {
        int k = k0 + 2 * kk;
        float f0 = W[(size_t)k * HH + n];
        float f1 = W[(size_t)(k + 1) * HH + n];
        uint32_t hi, lo;
        bf_split2(f0, f1, hi, lo);
        *(uint32_t*)(g_Wthi + base + k) = hi;
        *(uint32_t*)(g_Wtlo + base + k) = lo;
    }
}

// ---------------------------------------------------------------------------
// Merged QKV: one pass over x computes k, q, v. 128 rows x 192 cols per CTA,
// 256 threads (8 warps x m16). x fp32 read ONCE, split to hi/lo in-register.
// Outputs: K/Q split-bf16 row-major; V split-bf16 transposed [b][h][t].
// ---------------------------------------------------------------------------
#define QKV_SMEM (80*1024 + 1024)
__global__ __launch_bounds__(256)
void qkv_kernel(const float* __restrict__ x,
                const float* __restrict__ bk, const float* __restrict__ bq,
                const float* __restrict__ bv)
{
    extern __shared__ char dsm[];
    char* smc = (char*)(((uintptr_t)dsm + 1023) & ~(uintptr_t)1023);
    char* Xhi = smc;          char* Xlo = smc + 16384;
    char* Whi = smc + 32768;  char* Wlo = smc + 57344;   // 24KB each (192 rows)
    const uint32_t xhi_b = smem_u32(Xhi), xlo_b = smem_u32(Xlo);
    const uint32_t whi_b = smem_u32(Whi), wlo_b = smem_u32(Wlo);

    const int tid = threadIdx.x;
    const int wid = tid >> 5, lane = tid & 31;
    const int g = lane >> 2, t = lane & 3;
    const int R = 16 * wid;
    const int row0 = blockIdx.x * 128;

    float dD[24][4] = {};

#pragma unroll 1
    for (int kc = 0; kc < 16; kc++) {
        __syncthreads();
        // X chunk: fp32 -> hi/lo bf16, swizzled. 128 rows, thread=(r, half).
        {
            int r = tid >> 1, half = (tid & 1) * 32;
            const float* gp = x + (size_t)(row0 + r) * DD + kc * 64 + half;
#pragma unroll
            for (int i = 0; i < 4; i++) {
                float4 a = *(const float4*)(gp + 8 * i);
                float4 b = *(const float4*)(gp + 8 * i + 4);
                uint4 hi, lo;
                bf_split2(a.x, a.y, hi.x, lo.x);
                bf_split2(a.z, a.w, hi.y, lo.y);
                bf_split2(b.x, b.y, hi.z, lo.z);
                bf_split2(b.z, b.w, hi.w, lo.w);
                uint32_t off = swz((uint32_t)(r * 128 + half * 2 + 16 * i));
                *(uint4*)(Xhi + off) = hi;
                *(uint4*)(Xlo + off) = lo;
            }
        }
        // W chunk: 192 bf16 rows (stride DD), hi and lo.
#pragma unroll
        for (int pass = 0; pass < 2; pass++) {
            const unsigned short* gw = pass ? g_Wtlo : g_Wthi;
            char* sw = pass ? Wlo : Whi;
            for (int task = tid; task < 384; task += 256) {
                int rr = task >> 1, hf = task & 1;
                const char* gp = (const char*)(gw + (size_t)rr * DD + kc * 64 + hf * 32);
#pragma unroll
                for (int i = 0; i < 4; i++) {
                    uint4 v = *(const uint4*)(gp + 16 * i);
                    *(uint4*)(sw + swz((uint32_t)(rr * 128 + hf * 64 + 16 * i))) = v;
                }
            }
        }
        __syncthreads();

#pragma unroll
        for (int kk = 0; kk < 4; kk++) {
            uint32_t ah[4], al[4];
            ldA4(ah, xhi_b, R, kk);
            ldA4(al, xlo_b, R, kk);
#pragma unroll
            for (int jp = 0; jp < 12; jp++) {
                uint32_t wh[4], wl[4];
                ldB4(wh, whi_b, 2 * jp, kk);
                ldB4(wl, wlo_b, 2 * jp, kk);
                uint32_t bh0[2] = { wh[0], wh[1] }, bl0[2] = { wl[0], wl[1] };
                uint32_t bh1[2] = { wh[2], wh[3] }, bl1[2] = { wl[2], wl[3] };
                mma3(dD[2 * jp],     ah, al, bh0, bl0);
                mma3(dD[2 * jp + 1], ah, al, bh1, bl1);
            }
        }
    }

    const int r1 = R + g, r2 = r1 + 8;
    // K and Q: split directly to bf16 hi/lo, row-major.
#pragma unroll
    for (int grp = 0; grp < 2; grp++) {
        unsigned short* ohi = grp == 0 ? g_Khi : g_Qhi;
        unsigned short* olo = grp == 0 ? g_Klo : g_Qlo;
        const float* bias = grp == 0 ? bk : bq;
#pragma unroll
        for (int jj = 0; jj < 8; jj++) {
            int j = grp * 8 + jj;
            int c = 8 * jj + 2 * t;
            float b0 = bias[c], b1 = bias[c + 1];
            uint32_t hi, lo;
            bf_split2(dD[j][0] + b0, dD[j][1] + b1, hi, lo);
            *(uint32_t*)(ohi + (size_t)(row0 + r1) * HH + c) = hi;
            *(uint32_t*)(olo + (size_t)(row0 + r1) * HH + c) = lo;
            bf_split2(dD[j][2] + b0, dD[j][3] + b1, hi, lo);
            *(uint32_t*)(ohi + (size_t)(row0 + r2) * HH + c) = hi;
            *(uint32_t*)(olo + (size_t)(row0 + r2) * HH + c) = lo;
        }
    }
    // V: stage fp32 in smem (32KB, reuse X area), transpose-split to [h][t].
    __syncthreads();
    float* S = (float*)smc;
#pragma unroll
    for (int jj = 0; jj < 8; jj++) {
        int j = 16 + jj;
        int c = 8 * jj + 2 * t;
        float b0 = bv[c], b1 = bv[c + 1];
        S[r1 * 64 + c] = dD[j][0] + b0; S[r1 * 64 + c + 1] = dD[j][1] + b1;
        S[r2 * 64 + c] = dD[j][2] + b0; S[r2 * 64 + c + 1] = dD[j][3] + b1;
    }
    __syncthreads();
    {
        const int b    = row0 >> 12;
        const int tloc = row0 & (TT - 1);
        const int h  = tid & 63;
        const int s0 = (tid >> 6) * 32;
        const size_t obase = (size_t)b * HH * TT + (size_t)h * TT + tloc + s0;
#pragma unroll
        for (int jj = 0; jj < 32; jj += 8) {
            uint4 hi, lo;
            bf_split2(S[(s0 + jj + 0) * 64 + h], S[(s0 + jj + 1) * 64 + h], hi.x, lo.x);
            bf_split2(S[(s0 + jj + 2) * 64 + h], S[(s0 + jj + 3) * 64 + h], hi.y, lo.y);
            bf_split2(S[(s0 + jj + 4) * 64 + h], S[(s0 + jj + 5) * 64 + h], hi.z, lo.z);
            bf_split2(S[(s0 + jj + 6) * 64 + h], S[(s0 + jj + 7) * 64 + h], hi.w, lo.w);
            *(uint4*)(g_Vthi + obase + jj) = hi;
            *(uint4*)(g_Vtlo + obase + jj) = lo;
        }
    }
}

// ---------------------------------------------------------------------------
// HMMA flash attention (split-bf16, ldmatrix fragments). S[t][s] = k[t]·q[s]/8.
// CTA = 64 t-rows, 64-col s-tiles, 128 threads. K fragments hoisted.
// 2-way split-K -> 512 CTAs descending by work. Emits unnormalized (O, m, l).
// ---------------------------------------------------------------------------
__global__ __launch_bounds__(128)
void attn_mma_kernel()
{
    __shared__ __align__(1024) char sa[49152];
    char* Khi = sa;          char* Klo = sa + 8192;
    char* Qhi = sa + 16384;  char* Qlo = sa + 24576;
    char* Vhi = sa + 32768;  char* Vlo = sa + 40960;
    const uint32_t qhi_b = smem_u32(Qhi), qlo_b = smem_u32(Qlo);
    const uint32_t vhi_b = smem_u32(Vhi), vlo_b = smem_u32(Vlo);

    const int tid = threadIdx.x;
    const int wid = tid >> 5, lane = tid & 31;
    const int g = lane >> 2, t = lane & 3;
    const int R = 16 * wid;

    const int bid   = blockIdx.x;              // 0..511
    const int bt    = 63 - (bid >> 3);         // descending work order
    const int b     = (bid >> 1) & 3;
    const int split = bid & 1;
    const int sp    = (bt + 1) >> 1;
    const int st_lo = split ? sp : 0;
    const int st_hi = split ? bt : sp - 1;

    const size_t Rg = (size_t)b * TT + (size_t)bt * 64;
    const size_t vb = (size_t)b * HH * TT;
    const int trow1 = bt * 64 + R + g;
    const int trow2 = trow1 + 8;

    ldg_tile_bf(g_Khi + Rg * HH, HH, Khi, tid);
    ldg_tile_bf(g_Klo + Rg * HH, HH, Klo, tid);
    __syncthreads();
    uint32_t kfh[4][4], kfl[4][4];
#pragma unroll
    for (int kk = 0; kk < 4; kk++) {
        ldA(kfh[kk], Khi, R, g, t, kk);
        ldA(kfl[kk], Klo, R, g, t, kk);
    }

    float dO[8][4] = {};
    float m1 = -CUDART_INF_F, m2 = -CUDART_INF_F, l1 = 0.f, l2 = 0.f;

#pragma unroll 1
    for (int st = st_lo; st <= st_hi; st++) {
        __syncthreads();
        ldg_tile_bf(g_Qhi + ((size_t)b * TT + (size_t)st * 64) * HH, HH, Qhi, tid);
        ldg_tile_bf(g_Qlo + ((size_t)b * TT + (size_t)st * 64) * HH, HH, Qlo, tid);
        ldg_tile_bf(g_Vthi + vb + st * 64, TT, Vhi, tid);
        ldg_tile_bf(g_Vtlo + vb + st * 64, TT, Vlo, tid);
        __syncthreads();

        // ---- S = K @ Q^T ----
        float dS[8][4] = {};
#pragma unroll
        for (int kk = 0; kk < 4; kk++) {
#pragma unroll
            for (int jp = 0; jp < 4; jp++) {
                uint32_t qh[4], ql[4];
                ldB4(qh, qhi_b, 2 * jp, kk);
                ldB4(ql, qlo_b, 2 * jp, kk);
                uint32_t bh0[2] = { qh[0], qh[1] }, bl0[2] = { ql[0], ql[1] };
                uint32_t bh1[2] = { qh[2], qh[3] }, bl1[2] = { ql[2], ql[3] };
                mma3(dS[2 * jp],     kfh[kk], kfl[kk], bh0, bl0);
                mma3(dS[2 * jp + 1], kfh[kk], kfl[kk], bh1, bl1);
            }
        }

        // ---- scale + causal mask ----
        if (st == bt) {
#pragma unroll
            for (int j = 0; j < 8; j++) {
                int c0 = st * 64 + 8 * j + 2 * t;
                dS[j][0] = (c0     <= trow1) ? dS[j][0] * 0.125f : -1e30f;
                dS[j][1] = (c0 + 1 <= trow1) ? dS[j][1] * 0.125f : -1e30f;
                dS[j][2] = (c0     <= trow2) ? dS[j][2] * 0.125f : -1e30f;
                dS[j][3] = (c0 + 1 <= trow2) ? dS[j][3] * 0.125f : -1e30f;
            }
        } else {
#pragma unroll
            for (int j = 0; j < 8; j++) {
                dS[j][0] *= 0.125f; dS[j][1] *= 0.125f;
                dS[j][2] *= 0.125f; dS[j][3] *= 0.125f;
            }
        }

        // ---- online softmax ----
        float rmax1 = -CUDART_INF_F, rmax2 = -CUDART_INF_F;
#pragma unroll
        for (int j = 0; j < 8; j++) {
            rmax1 = fmaxf(rmax1, fmaxf(dS[j][0], dS[j][1]));
            rmax2 = fmaxf(rmax2, fmaxf(dS[j][2], dS[j][3]));
        }
        rmax1 = fmaxf(rmax1, __shfl_xor_sync(0xffffffffu, rmax1, 1));
        rmax1 = fmaxf(rmax1, __shfl_xor_sync(0xffffffffu, rmax1, 2));
        rmax2 = fmaxf(rmax2, __shfl_xor_sync(0xffffffffu, rmax2, 1));
        rmax2 = fmaxf(rmax2, __shfl_xor_sync(0xffffffffu, rmax2, 2));

        float mn1 = fmaxf(m1, rmax1), mn2 = fmaxf(m2, rmax2);
        float corr1 = __expf(m1 - mn1), corr2 = __expf(m2 - mn2);
        m1 = mn1; m2 = mn2;

        float sum1 = 0.f, sum2 = 0.f;
#pragma unroll
        for (int j = 0; j < 8; j++) {
            dS[j][0] = __expf(dS[j][0] - mn1);
            dS[j][1] = __expf(dS[j][1] - mn1);
            dS[j][2] = __expf(dS[j][2] - mn2);
            dS[j][3] = __expf(dS[j][3] - mn2);
            sum1 += dS[j][0] + dS[j][1];
            sum2 += dS[j][2] + dS[j][3];
        }
        sum1 += __shfl_xor_sync(0xffffffffu, sum1, 1);
        sum1 += __shfl_xor_sync(0xffffffffu, sum1, 2);
        sum2 += __shfl_xor_sync(0xffffffffu, sum2, 1);
        sum2 += __shfl_xor_sync(0xffffffffu, sum2, 2);
        l1 = l1 * corr1 + sum1;
        l2 = l2 * corr2 + sum2;
#pragma unroll
        for (int j = 0; j < 8; j++) {
            dO[j][0] *= corr1; dO[j][1] *= corr1;
            dO[j][2] *= corr2; dO[j][3] *= corr2;
        }

        // ---- O += P @ V (P fragments repacked in registers) ----
#pragma unroll
        for (int ss = 0; ss < 4; ss++) {
            uint32_t pah[4], pal[4];
            bf_split2(dS[2*ss][0],   dS[2*ss][1],   pah[0], pal[0]);
            bf_split2(dS[2*ss][2],   dS[2*ss][3],   pah[1], pal[1]);
            bf_split2(dS[2*ss+1][0], dS[2*ss+1][1], pah[2], pal[2]);
            bf_split2(dS[2*ss+1][2], dS[2*ss+1][3], pah[3], pal[3]);
#pragma unroll
            for (int jp = 0; jp < 4; jp++) {
                uint32_t vh[4], vl[4];
                ldB4(vh, vhi_b, 2 * jp, ss);
                ldB4(vl, vlo_b, 2 * jp, ss);
                uint32_t bh0[2] = { vh[0], vh[1] }, bl0[2] = { vl[0], vl[1] };
                uint32_t bh1[2] = { vh[2], vh[3] }, bl1[2] = { vl[2], vl[3] };
                mma3(dO[2 * jp],     pah, pal, bh0, bl0);
                mma3(dO[2 * jp + 1], pah, pal, bh1, bl1);
            }
        }
    }

    // ---- write unnormalized partial + (m, l) ----
    const size_t orow1 = (size_t)split * NROW + Rg + R + g;
    const size_t orow2 = orow1 + 8;
#pragma unroll
    for (int j = 0; j < 8; j++) {
        int c = 8 * j + 2 * t;
        *(float2*)(g_Oa + orow1 * HH + c) = make_float2(dO[j][0], dO[j][1]);
        *(float2*)(g_Oa + orow2 * HH + c) = make_float2(dO[j][2], dO[j][3]);
    }
    if (t == 0) {
        g_M[orow1] = m1; g_L[orow1] = l1;
        g_M[orow2] = m2; g_L[orow2] = l2;
    }
}

// ---------------------------------------------------------------------------
// Merge the two split partials.
// ---------------------------------------------------------------------------
__global__ __launch_bounds__(256)
void combine_kernel(float* __restrict__ out)
{
    int gid = blockIdx.x * 256 + threadIdx.x;
    int r = gid >> 4, lane = gid & 15;
    float m0 = g_M[r],  mm1 = g_M[NROW + r];
    float l0 = g_L[r],  ll1 = g_L[NROW + r];
    float M = fmaxf(m0, mm1);
    float e0 = __expf(m0 - M), e1 = __expf(mm1 - M);
    float inv = 1.0f / (l0 * e0 + ll1 * e1);
    float4 a = *(const float4*)(g_Oa + ((size_t)r) * HH + 4 * lane);
    float4 c = *(const float4*)(g_Oa + ((size_t)(NROW + r)) * HH + 4 * lane);
    float4 ov;
    ov.x = (a.x * e0 + c.x * e1) * inv;
    ov.y = (a.y * e0 + c.y * e1) * inv;
    ov.z = (a.z * e0 + c.z * e1) * inv;
    ov.w = (a.w * e0 + c.w * e1) * inv;
    *(float4*)(out + (size_t)r * HH + 4 * lane) = ov;
}

extern "C" void kernel_launch(void* const* d_in, const int* in_sizes, int n_in,
                              void* d_out, int out_size)
{
    const float* x  = (const float*)d_in[0];
    const float* Wk = (const float*)d_in[1];
    const float* bk = (const float*)d_in[2];
    const float* Wq = (const float*)d_in[3];
    const float* bq = (const float*)d_in[4];
    const float* Wv = (const float*)d_in[5];
    const float* bv = (const float*)d_in[6];
    float* out = (float*)d_out;

    static bool attr_done = false;
    if (!attr_done) {
        cudaFuncSetAttribute(qkv_kernel,
            cudaFuncAttributeMaxDynamicSharedMemorySize, QKV_SMEM);
        attr_done = true;
    }

    cvt_w_kernel<<<24, 128>>>(Wk, Wq, Wv);

    qkv_kernel<<<NROW / 128, 256, QKV_SMEM>>>(x, bk, bq, bv);

    attn_mma_kernel<<<512, 128>>>();

    combine_kernel<<<NROW * 16 / 256, 256>>>(out);
}

// round 9
// speedup vs baseline: 2.9858x; 1.1289x over previous
#include <cuda_runtime.h>
#include <cuda_bf16.h>
#include <math_constants.h>
#include <cstdint>

#define BB 4
#define TT 4096
#define DD 1024
#define HH 64
#define NROW (BB*TT)
#define NSPLIT 4

// Scratch — __device__ globals per allocation rules.
__device__ unsigned short g_Wthi[3*HH*DD];    // W^T split-bf16: [m][n][k]
__device__ unsigned short g_Wtlo[3*HH*DD];
__device__ unsigned short g_Khi[NROW*HH];     // k,q split-bf16 (row-major)
__device__ unsigned short g_Klo[NROW*HH];
__device__ unsigned short g_Qhi[NROW*HH];
__device__ unsigned short g_Qlo[NROW*HH];
__device__ unsigned short g_Vthi[BB*HH*TT];   // v split-bf16 TRANSPOSED: [b][h][t]
__device__ unsigned short g_Vtlo[BB*HH*TT];
__device__ float g_Oa[NSPLIT*NROW*HH];        // split partial O (unnormalized)
__device__ float g_M[NSPLIT*NROW];
__device__ float g_L[NSPLIT*NROW];

// ---------------- helpers ----------------
__device__ __forceinline__ uint32_t swz(uint32_t o) { return o ^ ((o >> 3) & 0x70); }

__device__ __forceinline__ uint32_t smem_u32(const void* p) {
    uint32_t a;
    asm("{ .reg .u64 t; cvta.to.shared.u64 t, %1; cvt.u32.u64 %0, t; }"
        : "=r"(a) : "l"(p));
    return a;
}

// FAST split: hi = truncate-to-bf16 (top 16 bits), lo = exact residual, RN.
// 6 instructions per pair (PRMT, 2 LOP3, 2 FADD, CVT.bf16x2).
__device__ __forceinline__ void bf_split2(float x0, float x1, uint32_t& hi, uint32_t& lo) {
    uint32_t u0 = __float_as_uint(x0), u1 = __float_as_uint(x1);
    hi = __byte_perm(u0, u1, 0x7632);            // {hi16(x1), hi16(x0)}
    float h0 = __uint_as_float(u0 & 0xFFFF0000u);
    float h1 = __uint_as_float(u1 & 0xFFFF0000u);
    float l0 = x0 - h0, l1 = x1 - h1;            // exact
    asm("cvt.rn.bf16x2.f32 %0, %1, %2;" : "=r"(lo) : "f"(l1), "f"(l0));
}

__device__ __forceinline__ void mma16816(float (&d)[4], const uint32_t (&a)[4],
                                         const uint32_t (&b)[2]) {
    asm volatile(
        "mma.sync.aligned.m16n8k16.row.col.f32.bf16.bf16.f32 "
        "{%0,%1,%2,%3}, {%4,%5,%6,%7}, {%8,%9}, {%0,%1,%2,%3};"
        : "+f"(d[0]), "+f"(d[1]), "+f"(d[2]), "+f"(d[3])
        : "r"(a[0]), "r"(a[1]), "r"(a[2]), "r"(a[3]), "r"(b[0]), "r"(b[1]));
}
__device__ __forceinline__ void mma3(float (&d)[4], const uint32_t (&ah)[4],
                                     const uint32_t (&al)[4], const uint32_t (&bh)[2],
                                     const uint32_t (&bl)[2]) {
    mma16816(d, ah, bh);
    mma16816(d, ah, bl);
    mma16816(d, al, bh);
}

__device__ __forceinline__ void ldsm4(uint32_t (&r)[4], uint32_t saddr) {
    asm volatile("ldmatrix.sync.aligned.m8n8.x4.shared.b16 {%0,%1,%2,%3}, [%4];"
        : "=r"(r[0]), "=r"(r[1]), "=r"(r[2]), "=r"(r[3]) : "r"(saddr));
}
// B fragments for n-tiles j and j+1, k-step kk, from row-major [n][k] SW128 tile.
__device__ __forceinline__ void ldB4(uint32_t (&r)[4], uint32_t base, int j, int kk) {
    int lane = threadIdx.x & 31;
    int rsel = lane & 7, sel = lane >> 3;
    uint32_t byte = (uint32_t)((8 * (j + (sel >> 1)) + rsel) * 128 + kk * 32 + (sel & 1) * 16);
    ldsm4(r, base + swz(byte));
}
// A fragments (rows R..R+15, k-step kk) from row-major SW128 tile.
__device__ __forceinline__ void ldA4(uint32_t (&r)[4], uint32_t base, int R, int kk) {
    int lane = threadIdx.x & 31;
    int rsel = lane & 7, sel = lane >> 3;
    uint32_t byte = (uint32_t)((R + (sel & 1) * 8 + rsel) * 128 + kk * 32 + (sel >> 1) * 16);
    ldsm4(r, base + swz(byte));
}
// scalar A load (used once for K hoist)
__device__ __forceinline__ void ldA(uint32_t (&a)[4], const char* s,
                                    int R, int g, int t, int kk) {
    uint32_t o0 = (uint32_t)((R + g) * 128 + kk * 32 + 4 * t);
    uint32_t o1 = o0 + 8 * 128;
    a[0] = *(const uint32_t*)(s + swz(o0));
    a[1] = *(const uint32_t*)(s + swz(o1));
    a[2] = *(const uint32_t*)(s + swz(o0 + 16));
    a[3] = *(const uint32_t*)(s + swz(o1 + 16));
}

// 64-row bf16 tile loader, 256 threads (2 uint4 each).
__device__ __forceinline__ void ldg_tile64_t256(const unsigned short* __restrict__ g,
                                                int lds, char* s, int tid) {
    int r = tid >> 2, q = tid & 3;
    const char* gp = (const char*)(g + (size_t)r * lds + q * 16);
#pragma unroll
    for (int i = 0; i < 2; i++) {
        uint4 v = *(const uint4*)(gp + 16 * i);
        *(uint4*)(s + swz((uint32_t)(r * 128 + q * 32 + 16 * i))) = v;
    }
}

// ---------------------------------------------------------------------------
// cvt_w: W[k][n] fp32 -> Wt[m][n][k] bf16 hi/lo. grid 24 x 128.
// ---------------------------------------------------------------------------
__global__ __launch_bounds__(128)
void cvt_w_kernel(const float* __restrict__ Wk, const float* __restrict__ Wq,
                  const float* __restrict__ Wv)
{
    const int m = blockIdx.x >> 3;
    const int n = (blockIdx.x & 7) * 8 + (threadIdx.x >> 4);
    const int k0 = (threadIdx.x & 15) * 64;
    const float* W = (m == 0) ? Wk : (m == 1) ? Wq : Wv;
    const size_t base = (size_t)m * HH * DD + (size_t)n * DD;
#pragma unroll 4
    for (int kk = 0; kk < 32; kk++) {
        int k = k0 + 2 * kk;
        float f0 = W[(size_t)k * HH + n];
        float f1 = W[(size_t)(k + 1) * HH + n];
        uint32_t hi, lo;
        bf_split2(f0, f1, hi, lo);
        *(uint32_t*)(g_Wthi + base + k) = hi;
        *(uint32_t*)(g_Wtlo + base + k) = lo;
    }
}

// ---------------------------------------------------------------------------
// Merged QKV: one pass over x computes k, q, v. 128 rows x 192 cols per CTA,
// 256 threads (8 warps x m16). x fp32 read ONCE, fast-split in-register.
// ---------------------------------------------------------------------------
#define QKV_SMEM (80*1024 + 1024)
__global__ __launch_bounds__(256)
void qkv_kernel(const float* __restrict__ x,
                const float* __restrict__ bk, const float* __restrict__ bq,
                const float* __restrict__ bv)
{
    extern __shared__ char dsm[];
    char* smc = (char*)(((uintptr_t)dsm + 1023) & ~(uintptr_t)1023);
    char* Xhi = smc;          char* Xlo = smc + 16384;
    char* Whi = smc + 32768;  char* Wlo = smc + 57344;   // 24KB each (192 rows)
    const uint32_t xhi_b = smem_u32(Xhi), xlo_b = smem_u32(Xlo);
    const uint32_t whi_b = smem_u32(Whi), wlo_b = smem_u32(Wlo);

    const int tid = threadIdx.x;
    const int wid = tid >> 5, lane = tid & 31;
    const int g = lane >> 2, t = lane & 3;
    const int R = 16 * wid;
    const int row0 = blockIdx.x * 128;

    float dD[24][4] = {};

#pragma unroll 1
    for (int kc = 0; kc < 16; kc++) {
        __syncthreads();
        {
            int r = tid >> 1, half = (tid & 1) * 32;
            const float* gp = x + (size_t)(row0 + r) * DD + kc * 64 + half;
#pragma unroll
            for (int i = 0; i < 4; i++) {
                float4 a = *(const float4*)(gp + 8 * i);
                float4 b = *(const float4*)(gp + 8 * i + 4);
                uint4 hi, lo;
                bf_split2(a.x, a.y, hi.x, lo.x);
                bf_split2(a.z, a.w, hi.y, lo.y);
                bf_split2(b.x, b.y, hi.z, lo.z);
                bf_split2(b.z, b.w, hi.w, lo.w);
                uint32_t off = swz((uint32_t)(r * 128 + half * 2 + 16 * i));
                *(uint4*)(Xhi + off) = hi;
                *(uint4*)(Xlo + off) = lo;
            }
        }
#pragma unroll
        for (int pass = 0; pass < 2; pass++) {
            const unsigned short* gw = pass ? g_Wtlo : g_Wthi;
            char* sw = pass ? Wlo : Whi;
            for (int task = tid; task < 384; task += 256) {
                int rr = task >> 1, hf = task & 1;
                const char* gp = (const char*)(gw + (size_t)rr * DD + kc * 64 + hf * 32);
#pragma unroll
                for (int i = 0; i < 4; i++) {
                    uint4 v = *(const uint4*)(gp + 16 * i);
                    *(uint4*)(sw + swz((uint32_t)(rr * 128 + hf * 64 + 16 * i))) = v;
                }
            }
        }
        __syncthreads();

#pragma unroll
        for (int kk = 0; kk < 4; kk++) {
            uint32_t ah[4], al[4];
            ldA4(ah, xhi_b, R, kk);
            ldA4(al, xlo_b, R, kk);
#pragma unroll
            for (int jp = 0; jp < 12; jp++) {
                uint32_t wh[4], wl[4];
                ldB4(wh, whi_b, 2 * jp, kk);
                ldB4(wl, wlo_b, 2 * jp, kk);
                uint32_t bh0[2] = { wh[0], wh[1] }, bl0[2] = { wl[0], wl[1] };
                uint32_t bh1[2] = { wh[2], wh[3] }, bl1[2] = { wl[2], wl[3] };
                mma3(dD[2 * jp],     ah, al, bh0, bl0);
                mma3(dD[2 * jp + 1], ah, al, bh1, bl1);
            }
        }
    }

    const int r1 = R + g, r2 = r1 + 8;
#pragma unroll
    for (int grp = 0; grp < 2; grp++) {
        unsigned short* ohi = grp == 0 ? g_Khi : g_Qhi;
        unsigned short* olo = grp == 0 ? g_Klo : g_Qlo;
        const float* bias = grp == 0 ? bk : bq;
#pragma unroll
        for (int jj = 0; jj < 8; jj++) {
            int j = grp * 8 + jj;
            int c = 8 * jj + 2 * t;
            float b0 = bias[c], b1 = bias[c + 1];
            uint32_t hi, lo;
            bf_split2(dD[j][0] + b0, dD[j][1] + b1, hi, lo);
            *(uint32_t*)(ohi + (size_t)(row0 + r1) * HH + c) = hi;
            *(uint32_t*)(olo + (size_t)(row0 + r1) * HH + c) = lo;
            bf_split2(dD[j][2] + b0, dD[j][3] + b1, hi, lo);
            *(uint32_t*)(ohi + (size_t)(row0 + r2) * HH + c) = hi;
            *(uint32_t*)(olo + (size_t)(row0 + r2) * HH + c) = lo;
        }
    }
    // V: stage fp32 in smem (32KB, reuse X area), transpose-split to [h][t].
    __syncthreads();
    float* S = (float*)smc;
#pragma unroll
    for (int jj = 0; jj < 8; jj++) {
        int j = 16 + jj;
        int c = 8 * jj + 2 * t;
        float b0 = bv[c], b1 = bv[c + 1];
        S[r1 * 64 + c] = dD[j][0] + b0; S[r1 * 64 + c + 1] = dD[j][1] + b1;
        S[r2 * 64 + c] = dD[j][2] + b0; S[r2 * 64 + c + 1] = dD[j][3] + b1;
    }
    __syncthreads();
    {
        const int b    = row0 >> 12;
        const int tloc = row0 & (TT - 1);
        const int h  = tid & 63;
        const int s0 = (tid >> 6) * 32;
        const size_t obase = (size_t)b * HH * TT + (size_t)h * TT + tloc + s0;
#pragma unroll
        for (int jj = 0; jj < 32; jj += 8) {
            uint4 hi, lo;
            bf_split2(S[(s0 + jj + 0) * 64 + h], S[(s0 + jj + 1) * 64 + h], hi.x, lo.x);
            bf_split2(S[(s0 + jj + 2) * 64 + h], S[(s0 + jj + 3) * 64 + h], hi.y, lo.y);
            bf_split2(S[(s0 + jj + 4) * 64 + h], S[(s0 + jj + 5) * 64 + h], hi.z, lo.z);
            bf_split2(S[(s0 + jj + 6) * 64 + h], S[(s0 + jj + 7) * 64 + h], hi.w, lo.w);
            *(uint4*)(g_Vthi + obase + jj) = hi;
            *(uint4*)(g_Vtlo + obase + jj) = lo;
        }
    }
}

// ---------------------------------------------------------------------------
// HMMA flash attention. CTA = 128 t-rows (8 warps), 64-col s-tiles.
// K smem reused for Q/V after fragment hoist (32KB static). 4-way split-K ->
// 512 CTAs descending by work. Emits unnormalized (O, m, l) per split.
// ---------------------------------------------------------------------------
__global__ __launch_bounds__(256)
void attn_mma_kernel()
{
    __shared__ __align__(1024) char sa[32768];
    char* Qhi = sa;          char* Qlo = sa + 8192;
    char* Vhi = sa + 16384;  char* Vlo = sa + 24576;
    const uint32_t sa_b = smem_u32(sa);
    const uint32_t qhi_b = sa_b, qlo_b = sa_b + 8192;
    const uint32_t vhi_b = sa_b + 16384, vlo_b = sa_b + 24576;

    const int tid = threadIdx.x;
    const int wid = tid >> 5, lane = tid & 31;
    const int g = lane >> 2, t = lane & 3;
    const int R = 16 * wid;                     // warp rows within 128-row tile

    const int bid   = blockIdx.x;               // 0..511
    const int bt    = 31 - (bid >> 4);          // descending work order
    const int sub   = bid & 15;
    const int b     = sub >> 2;
    const int split = sub & 3;
    const int n     = 2 * bt + 2;               // s-tiles covering this row-tile
    const int st_lo = (split * n) >> 2;
    const int st_hi = (((split + 1) * n) >> 2) - 1;

    const size_t Rg = (size_t)b * TT + (size_t)bt * 128;
    const size_t vb = (size_t)b * HH * TT;
    const int trow1 = bt * 128 + R + g;
    const int trow2 = trow1 + 8;

    // K: 128x64 hi/lo into ALL of smem, hoist fragments, then reuse for Q/V.
    {
        int r = tid >> 1, half = tid & 1;
        const char* gph = (const char*)(g_Khi + (Rg + r) * HH + half * 32);
        const char* gpl = (const char*)(g_Klo + (Rg + r) * HH + half * 32);
#pragma unroll
        for (int i = 0; i < 4; i++) {
            uint4 vh = *(const uint4*)(gph + 16 * i);
            uint4 vl = *(const uint4*)(gpl + 16 * i);
            uint32_t off = swz((uint32_t)(r * 128 + half * 64 + 16 * i));
            *(uint4*)(sa + off) = vh;
            *(uint4*)(sa + 16384 + off) = vl;
        }
    }
    __syncthreads();
    uint32_t kfh[4][4], kfl[4][4];
#pragma unroll
    for (int kk = 0; kk < 4; kk++) {
        ldA(kfh[kk], sa, R, g, t, kk);
        ldA(kfl[kk], sa + 16384, R, g, t, kk);
    }

    float dO[8][4] = {};
    float m1 = -CUDART_INF_F, m2 = -CUDART_INF_F, l1 = 0.f, l2 = 0.f;

#pragma unroll 1
    for (int st = st_lo; st <= st_hi; st++) {
        __syncthreads();   // K-hoist done (first iter) / prev LDS done
        ldg_tile64_t256(g_Qhi + ((size_t)b * TT + (size_t)st * 64) * HH, HH, Qhi, tid);
        ldg_tile64_t256(g_Qlo + ((size_t)b * TT + (size_t)st * 64) * HH, HH, Qlo, tid);
        ldg_tile64_t256(g_Vthi + vb + st * 64, TT, Vhi, tid);
        ldg_tile64_t256(g_Vtlo + vb + st * 64, TT, Vlo, tid);
        __syncthreads();

        // ---- S = K @ Q^T ----
        float dS[8][4] = {};
#pragma unroll
        for (int kk = 0; kk < 4; kk++) {
#pragma unroll
            for (int jp = 0; jp < 4; jp++) {
                uint32_t qh[4], ql[4];
                ldB4(qh, qhi_b, 2 * jp, kk);
                ldB4(ql, qlo_b, 2 * jp, kk);
                uint32_t bh0[2] = { qh[0], qh[1] }, bl0[2] = { ql[0], ql[1] };
                uint32_t bh1[2] = { qh[2], qh[3] }, bl1[2] = { ql[2], ql[3] };
                mma3(dS[2 * jp],     kfh[kk], kfl[kk], bh0, bl0);
                mma3(dS[2 * jp + 1], kfh[kk], kfl[kk], bh1, bl1);
            }
        }

        // ---- scale + causal mask (tile can cross diagonal when st >= 2bt) ----
        if (st >= 2 * bt) {
#pragma unroll
            for (int j = 0; j < 8; j++) {
                int c0 = st * 64 + 8 * j + 2 * t;
                dS[j][0] = (c0     <= trow1) ? dS[j][0] * 0.125f : -1e30f;
                dS[j][1] = (c0 + 1 <= trow1) ? dS[j][1] * 0.125f : -1e30f;
                dS[j][2] = (c0     <= trow2) ? dS[j][2] * 0.125f : -1e30f;
                dS[j][3] = (c0 + 1 <= trow2) ? dS[j][3] * 0.125f : -1e30f;
            }
        } else {
#pragma unroll
            for (int j = 0; j < 8; j++) {
                dS[j][0] *= 0.125f; dS[j][1] *= 0.125f;
                dS[j][2] *= 0.125f; dS[j][3] *= 0.125f;
            }
        }

        // ---- online softmax ----
        float rmax1 = -CUDART_INF_F, rmax2 = -CUDART_INF_F;
#pragma unroll
        for (int j = 0; j < 8; j++) {
            rmax1 = fmaxf(rmax1, fmaxf(dS[j][0], dS[j][1]));
            rmax2 = fmaxf(rmax2, fmaxf(dS[j][2], dS[j][3]));
        }
        rmax1 = fmaxf(rmax1, __shfl_xor_sync(0xffffffffu, rmax1, 1));
        rmax1 = fmaxf(rmax1, __shfl_xor_sync(0xffffffffu, rmax1, 2));
        rmax2 = fmaxf(rmax2, __shfl_xor_sync(0xffffffffu, rmax2, 1));
        rmax2 = fmaxf(rmax2, __shfl_xor_sync(0xffffffffu, rmax2, 2));

        float mn1 = fmaxf(m1, rmax1), mn2 = fmaxf(m2, rmax2);
        float corr1 = __expf(m1 - mn1), corr2 = __expf(m2 - mn2);
        m1 = mn1; m2 = mn2;

        float sum1 = 0.f, sum2 = 0.f;
#pragma unroll
        for (int j = 0; j < 8; j++) {
            dS[j][0] = __expf(dS[j][0] - mn1);
            dS[j][1] = __expf(dS[j][1] - mn1);
            dS[j][2] = __expf(dS[j][2] - mn2);
            dS[j][3] = __expf(dS[j][3] - mn2);
            sum1 += dS[j][0] + dS[j][1];
            sum2 += dS[j][2] + dS[j][3];
        }
        sum1 += __shfl_xor_sync(0xffffffffu, sum1, 1);
        sum1 += __shfl_xor_sync(0xffffffffu, sum1, 2);
        sum2 += __shfl_xor_sync(0xffffffffu, sum2, 1);
        sum2 += __shfl_xor_sync(0xffffffffu, sum2, 2);
        l1 = l1 * corr1 + sum1;
        l2 = l2 * corr2 + sum2;
#pragma unroll
        for (int j = 0; j < 8; j++) {
            dO[j][0] *= corr1; dO[j][1] *= corr1;
            dO[j][2] *= corr2; dO[j][3] *= corr2;
        }

        // ---- O += P @ V (P fragments repacked in registers) ----
#pragma unroll
        for (int ss = 0; ss < 4; ss++) {
            uint32_t pah[4], pal[4];
            bf_split2(dS[2*ss][0],   dS[2*ss][1],   pah[0], pal[0]);
            bf_split2(dS[2*ss][2],   dS[2*ss][3],   pah[1], pal[1]);
            bf_split2(dS[2*ss+1][0], dS[2*ss+1][1], pah[2], pal[2]);
            bf_split2(dS[2*ss+1][2], dS[2*ss+1][3], pah[3], pal[3]);
#pragma unroll
            for (int jp = 0; jp < 4; jp++) {
                uint32_t vh[4], vl[4];
                ldB4(vh, vhi_b, 2 * jp, ss);
                ldB4(vl, vlo_b, 2 * jp, ss);
                uint32_t bh0[2] = { vh[0], vh[1] }, bl0[2] = { vl[0], vl[1] };
                uint32_t bh1[2] = { vh[2], vh[3] }, bl1[2] = { vl[2], vl[3] };
                mma3(dO[2 * jp],     pah, pal, bh0, bl0);
                mma3(dO[2 * jp + 1], pah, pal, bh1, bl1);
            }
        }
    }

    // ---- write unnormalized partial + (m, l) ----
    const size_t orow1 = (size_t)split * NROW + Rg + R + g;
    const size_t orow2 = orow1 + 8;
#pragma unroll
    for (int j = 0; j < 8; j++) {
        int c = 8 * j + 2 * t;
        *(float2*)(g_Oa + orow1 * HH + c) = make_float2(dO[j][0], dO[j][1]);
        *(float2*)(g_Oa + orow2 * HH + c) = make_float2(dO[j][2], dO[j][3]);
    }
    if (t == 0) {
        g_M[orow1] = m1; g_L[orow1] = l1;
        g_M[orow2] = m2; g_L[orow2] = l2;
    }
}

// ---------------------------------------------------------------------------
// Merge the four split partials.
// ---------------------------------------------------------------------------
__global__ __launch_bounds__(256)
void combine_kernel(float* __restrict__ out)
{
    int gid = blockIdx.x * 256 + threadIdx.x;
    int r = gid >> 4, lane = gid & 15;
    float m[NSPLIT], l[NSPLIT];
#pragma unroll
    for (int i = 0; i < NSPLIT; i++) {
        m[i] = g_M[(size_t)i * NROW + r];
        l[i] = g_L[(size_t)i * NROW + r];
    }
    float M = fmaxf(fmaxf(m[0], m[1]), fmaxf(m[2], m[3]));
    float denom = 0.f, e[NSPLIT];
#pragma unroll
    for (int i = 0; i < NSPLIT; i++) {
        e[i] = __expf(m[i] - M);       // exp(-inf)=0 for empty splits
        denom += l[i] * e[i];
    }
    float inv = 1.0f / denom;
    float4 acc = make_float4(0.f, 0.f, 0.f, 0.f);
#pragma unroll
    for (int i = 0; i < NSPLIT; i++) {
        float4 a = *(const float4*)(g_Oa + ((size_t)i * NROW + r) * HH + 4 * lane);
        acc.x += a.x * e[i]; acc.y += a.y * e[i];
        acc.z += a.z * e[i]; acc.w += a.w * e[i];
    }
    acc.x *= inv; acc.y *= inv; acc.z *= inv; acc.w *= inv;
    *(float4*)(out + (size_t)r * HH + 4 * lane) = acc;
}

extern "C" void kernel_launch(void* const* d_in, const int* in_sizes, int n_in,
                              void* d_out, int out_size)
{
    const float* x  = (const float*)d_in[0];
    const float* Wk = (const float*)d_in[1];
    const float* bk = (const float*)d_in[2];
    const float* Wq = (const float*)d_in[3];
    const float* bq = (const float*)d_in[4];
    const float* Wv = (const float*)d_in[5];
    const float* bv = (const float*)d_in[6];
    float* out = (float*)d_out;

    static bool attr_done = false;
    if (!attr_done) {
        cudaFuncSetAttribute(qkv_kernel,
            cudaFuncAttributeMaxDynamicSharedMemorySize, QKV_SMEM);
        attr_done = true;
    }

    cvt_w_kernel<<<24, 128>>>(Wk, Wq, Wv);

    qkv_kernel<<<NROW / 128, 256, QKV_SMEM>>>(x, bk, bq, bv);

    attn_mma_kernel<<<512, 256>>>();   // 32 row-tiles x 4 batch x 4 splits

    combine_kernel<<<NROW * 16 / 256, 256>>>(out);
}

// round 10
// speedup vs baseline: 3.5884x; 1.2018x over previous
#include <cuda_runtime.h>
#include <cuda_bf16.h>
#include <math_constants.h>
#include <cstdint>

#define BB 4
#define TT 4096
#define DD 1024
#define HH 64
#define NROW (BB*TT)
#define NSPLIT 4

// Scratch — __device__ globals per allocation rules.
__device__ unsigned short g_Wthi[3*HH*DD];    // W^T split-bf16: [m][n][k]
__device__ unsigned short g_Wtlo[3*HH*DD];
__device__ unsigned short g_Khi[NROW*HH];     // k,q split-bf16 (row-major)
__device__ unsigned short g_Klo[NROW*HH];
__device__ unsigned short g_Qhi[NROW*HH];
__device__ unsigned short g_Qlo[NROW*HH];
__device__ unsigned short g_Vthi[BB*HH*TT];   // v split-bf16 TRANSPOSED: [b][h][t]
__device__ unsigned short g_Vtlo[BB*HH*TT];
__device__ float g_Oa[NSPLIT*NROW*HH];        // split partial O (unnormalized)
__device__ float g_M[NSPLIT*NROW];
__device__ float g_L[NSPLIT*NROW];

// ---------------- helpers ----------------
__device__ __forceinline__ uint32_t swz(uint32_t o) { return o ^ ((o >> 3) & 0x70); }

__device__ __forceinline__ uint32_t smem_u32(const void* p) {
    uint32_t a;
    asm("{ .reg .u64 t; cvta.to.shared.u64 t, %1; cvt.u32.u64 %0, t; }"
        : "=r"(a) : "l"(p));
    return a;
}

// FAST split: hi = truncate-to-bf16 (top 16 bits), lo = exact residual, RN.
__device__ __forceinline__ void bf_split2(float x0, float x1, uint32_t& hi, uint32_t& lo) {
    uint32_t u0 = __float_as_uint(x0), u1 = __float_as_uint(x1);
    hi = __byte_perm(u0, u1, 0x7632);            // {hi16(x1), hi16(x0)}
    float h0 = __uint_as_float(u0 & 0xFFFF0000u);
    float h1 = __uint_as_float(u1 & 0xFFFF0000u);
    float l0 = x0 - h0, l1 = x1 - h1;            // exact
    asm("cvt.rn.bf16x2.f32 %0, %1, %2;" : "=r"(lo) : "f"(l1), "f"(l0));
}

__device__ __forceinline__ void mma16816(float (&d)[4], const uint32_t (&a)[4],
                                         const uint32_t (&b)[2]) {
    asm volatile(
        "mma.sync.aligned.m16n8k16.row.col.f32.bf16.bf16.f32 "
        "{%0,%1,%2,%3}, {%4,%5,%6,%7}, {%8,%9}, {%0,%1,%2,%3};"
        : "+f"(d[0]), "+f"(d[1]), "+f"(d[2]), "+f"(d[3])
        : "r"(a[0]), "r"(a[1]), "r"(a[2]), "r"(a[3]), "r"(b[0]), "r"(b[1]));
}
__device__ __forceinline__ void mma3(float (&d)[4], const uint32_t (&ah)[4],
                                     const uint32_t (&al)[4], const uint32_t (&bh)[2],
                                     const uint32_t (&bl)[2]) {
    mma16816(d, ah, bh);
    mma16816(d, ah, bl);
    mma16816(d, al, bh);
}

__device__ __forceinline__ void ldsm4(uint32_t (&r)[4], uint32_t saddr) {
    asm volatile("ldmatrix.sync.aligned.m8n8.x4.shared.b16 {%0,%1,%2,%3}, [%4];"
        : "=r"(r[0]), "=r"(r[1]), "=r"(r[2]), "=r"(r[3]) : "r"(saddr));
}
// B fragments for n-tiles j and j+1, k-step kk, from row-major [n][k] SW128 tile.
__device__ __forceinline__ void ldB4(uint32_t (&r)[4], uint32_t base, int j, int kk) {
    int lane = threadIdx.x & 31;
    int rsel = lane & 7, sel = lane >> 3;
    uint32_t byte = (uint32_t)((8 * (j + (sel >> 1)) + rsel) * 128 + kk * 32 + (sel & 1) * 16);
    ldsm4(r, base + swz(byte));
}
// A fragments (rows R..R+15, k-step kk) from row-major SW128 tile.
__device__ __forceinline__ void ldA4(uint32_t (&r)[4], uint32_t base, int R, int kk) {
    int lane = threadIdx.x & 31;
    int rsel = lane & 7, sel = lane >> 3;
    uint32_t byte = (uint32_t)((R + (sel & 1) * 8 + rsel) * 128 + kk * 32 + (sel >> 1) * 16);
    ldsm4(r, base + swz(byte));
}
// scalar A load (used once for K hoist)
__device__ __forceinline__ void ldA(uint32_t (&a)[4], const char* s,
                                    int R, int g, int t, int kk) {
    uint32_t o0 = (uint32_t)((R + g) * 128 + kk * 32 + 4 * t);
    uint32_t o1 = o0 + 8 * 128;
    a[0] = *(const uint32_t*)(s + swz(o0));
    a[1] = *(const uint32_t*)(s + swz(o1));
    a[2] = *(const uint32_t*)(s + swz(o0 + 16));
    a[3] = *(const uint32_t*)(s + swz(o1 + 16));
}

// ---- cp.async (LDGSTS) helpers ----
__device__ __forceinline__ void cp16(uint32_t dst, const void* src) {
    asm volatile("cp.async.cg.shared.global [%0], [%1], 16;" :: "r"(dst), "l"(src));
}
#define CP_COMMIT() asm volatile("cp.async.commit_group;" ::: "memory")
#define CP_WAIT(n)  asm volatile("cp.async.wait_group %0;" :: "n"(n) : "memory")

// async-load a 64x64 bf16 tile (row stride lds ushorts) into SW128 smem. 256 thr.
__device__ __forceinline__ void cp_tile64(const unsigned short* __restrict__ g,
                                          int lds, uint32_t sbase, int tid) {
    int r = tid >> 2, q = tid & 3;
    const char* gp = (const char*)(g + (size_t)r * lds + q * 16);
    uint32_t o = (uint32_t)(r * 128 + q * 32);
    cp16(sbase + swz(o), gp);
    cp16(sbase + swz(o + 16), gp + 16);
}

// ---------------------------------------------------------------------------
// cvt_w: W[k][n] fp32 -> Wt[m][n][k] bf16 hi/lo. grid 24 x 128.
// ---------------------------------------------------------------------------
__global__ __launch_bounds__(128)
void cvt_w_kernel(const float* __restrict__ Wk, const float* __restrict__ Wq,
                  const float* __restrict__ Wv)
{
    const int m = blockIdx.x >> 3;
    const int n = (blockIdx.x & 7) * 8 + (threadIdx.x >> 4);
    const int k0 = (threadIdx.x & 15) * 64;
    const float* W = (m == 0) ? Wk : (m == 1) ? Wq : Wv;
    const size_t base = (size_t)m * HH * DD + (size_t)n * DD;
#pragma unroll 4
    for (int kk = 0; kk < 32; kk++) {
        int k = k0 + 2 * kk;
        float f0 = W[(size_t)k * HH + n];
        float f1 = W[(size_t)(k + 1) * HH + n];
        uint32_t hi, lo;
        bf_split2(f0, f1, hi, lo);
        *(uint32_t*)(g_Wthi + base + k) = hi;
        *(uint32_t*)(g_Wtlo + base + k) = lo;
    }
}

// ---------------------------------------------------------------------------
// Merged QKV: 64 rows x 192 cols per CTA (256 CTAs -> all SMs busy).
// 256 threads = 4 row-warps x 2 col-groups (6 n-tile-pairs each).
// W tiles via cp.async (overlapped with X load/split/STS each chunk).
// ---------------------------------------------------------------------------
#define QKV_SMEM (65536 + 1024)
__global__ __launch_bounds__(256)
void qkv_kernel(const float* __restrict__ x,
                const float* __restrict__ bk, const float* __restrict__ bq,
                const float* __restrict__ bv)
{
    extern __shared__ char dsm[];
    char* smc = (char*)(((uintptr_t)dsm + 1023) & ~(uintptr_t)1023);
    char* Xhi = smc;          char* Xlo = smc + 8192;
    char* Whi = smc + 16384;  char* Wlo = smc + 40960;   // 24KB each (192 rows)
    const uint32_t xhi_b = smem_u32(Xhi), xlo_b = smem_u32(Xlo);
    const uint32_t whi_b = smem_u32(Whi), wlo_b = smem_u32(Wlo);

    const int tid = threadIdx.x;
    const int wid = tid >> 5, lane = tid & 31;
    const int g = lane >> 2, t = lane & 3;
    const int rw = wid & 3, cg = wid >> 2;
    const int R = 16 * rw;
    const int row0 = blockIdx.x * 64;

    float dD[12][4] = {};

#pragma unroll 1
    for (int kc = 0; kc < 16; kc++) {
        __syncthreads();   // previous MMA phase done with X/W smem
        // ---- W chunk via cp.async: 192 rows hi + 192 rows lo ----
        for (int task = tid; task < 768; task += 256) {
            int isLo = task >= 384;
            int tk = isLo ? task - 384 : task;
            int rr = tk >> 1, hf = tk & 1;
            const unsigned short* gw = isLo ? g_Wtlo : g_Wthi;
            uint32_t sb = isLo ? wlo_b : whi_b;
            const char* gp = (const char*)(gw + (size_t)rr * DD + kc * 64 + hf * 32);
#pragma unroll
            for (int i = 0; i < 4; i++)
                cp16(sb + swz((uint32_t)(rr * 128 + hf * 64 + 16 * i)), gp + 16 * i);
        }
        CP_COMMIT();
        // ---- X chunk: fp32 LDG + fast-split + STS (overlaps W cp.async) ----
        {
            int r = tid >> 2, q = tid & 3;
            const float* gp = x + (size_t)(row0 + r) * DD + kc * 64 + q * 16;
            float4 a0 = *(const float4*)(gp);
            float4 a1 = *(const float4*)(gp + 4);
            float4 a2 = *(const float4*)(gp + 8);
            float4 a3 = *(const float4*)(gp + 12);
            uint4 hi, lo;
            bf_split2(a0.x, a0.y, hi.x, lo.x);
            bf_split2(a0.z, a0.w, hi.y, lo.y);
            bf_split2(a1.x, a1.y, hi.z, lo.z);
            bf_split2(a1.z, a1.w, hi.w, lo.w);
            uint32_t off = swz((uint32_t)(r * 128 + q * 32));
            *(uint4*)(Xhi + off) = hi;
            *(uint4*)(Xlo + off) = lo;
            bf_split2(a2.x, a2.y, hi.x, lo.x);
            bf_split2(a2.z, a2.w, hi.y, lo.y);
            bf_split2(a3.x, a3.y, hi.z, lo.z);
            bf_split2(a3.z, a3.w, hi.w, lo.w);
            off = swz((uint32_t)(r * 128 + q * 32 + 16));
            *(uint4*)(Xhi + off) = hi;
            *(uint4*)(Xlo + off) = lo;
        }
        CP_WAIT(0);
        __syncthreads();

        // ---- MMA: this warp's 6 n-tile-pairs ----
#pragma unroll
        for (int kk = 0; kk < 4; kk++) {
            uint32_t ah[4], al[4];
            ldA4(ah, xhi_b, R, kk);
            ldA4(al, xlo_b, R, kk);
#pragma unroll
            for (int jl = 0; jl < 6; jl++) {
                uint32_t wh[4], wl[4];
                ldB4(wh, whi_b, cg * 12 + 2 * jl, kk);
                ldB4(wl, wlo_b, cg * 12 + 2 * jl, kk);
                uint32_t bh0[2] = { wh[0], wh[1] }, bl0[2] = { wl[0], wl[1] };
                uint32_t bh1[2] = { wh[2], wh[3] }, bl1[2] = { wl[2], wl[3] };
                mma3(dD[2 * jl],     ah, al, bh0, bl0);
                mma3(dD[2 * jl + 1], ah, al, bh1, bl1);
            }
        }
    }

    // ---- epilogue: K/Q straight to gmem (split-bf16); V staged for transpose ----
    const int r1 = R + g, r2 = r1 + 8;           // rows within 64-row tile
    float* Vst = (float*)smc;                    // 16KB fp32 stage (X area)
    __syncthreads();                             // MMA reads done
#pragma unroll
    for (int jl = 0; jl < 12; jl++) {
        int jt = cg * 12 + jl;
        int cgl = 8 * jt + 2 * t;                // global col 0..191
        int mi = cgl >> 6, cm = cgl & 63;
        if (mi < 2) {
            const float* bias = mi ? bq : bk;
            unsigned short* ohi = mi ? g_Qhi : g_Khi;
            unsigned short* olo = mi ? g_Qlo : g_Klo;
            float b0 = bias[cm], b1 = bias[cm + 1];
            uint32_t hi, lo;
            bf_split2(dD[jl][0] + b0, dD[jl][1] + b1, hi, lo);
            *(uint32_t*)(ohi + (size_t)(row0 + r1) * HH + cm) = hi;
            *(uint32_t*)(olo + (size_t)(row0 + r1) * HH + cm) = lo;
            bf_split2(dD[jl][2] + b0, dD[jl][3] + b1, hi, lo);
            *(uint32_t*)(ohi + (size_t)(row0 + r2) * HH + cm) = hi;
            *(uint32_t*)(olo + (size_t)(row0 + r2) * HH + cm) = lo;
        } else {
            float b0 = bv[cm], b1 = bv[cm + 1];
            Vst[r1 * 64 + cm] = dD[jl][0] + b0;
            Vst[r1 * 64 + cm + 1] = dD[jl][1] + b1;
            Vst[r2 * 64 + cm] = dD[jl][2] + b0;
            Vst[r2 * 64 + cm + 1] = dD[jl][3] + b1;
        }
    }
    __syncthreads();
    {   // transpose-split V: [s][h] -> g_Vt[b][h][t]
        const int b    = row0 >> 12;
        const int tloc = row0 & (TT - 1);
        const int h  = tid & 63;
        const int s0 = (tid >> 6) * 16;
        const size_t obase = (size_t)b * HH * TT + (size_t)h * TT + tloc + s0;
#pragma unroll
        for (int jj = 0; jj < 16; jj += 8) {
            uint4 hi, lo;
            bf_split2(Vst[(s0 + jj + 0) * 64 + h], Vst[(s0 + jj + 1) * 64 + h], hi.x, lo.x);
            bf_split2(Vst[(s0 + jj + 2) * 64 + h], Vst[(s0 + jj + 3) * 64 + h], hi.y, lo.y);
            bf_split2(Vst[(s0 + jj + 4) * 64 + h], Vst[(s0 + jj + 5) * 64 + h], hi.z, lo.z);
            bf_split2(Vst[(s0 + jj + 6) * 64 + h], Vst[(s0 + jj + 7) * 64 + h], hi.w, lo.w);
            *(uint4*)(g_Vthi + obase + jj) = hi;
            *(uint4*)(g_Vtlo + obase + jj) = lo;
        }
    }
}

// ---------------------------------------------------------------------------
// HMMA flash attention with cp.async double-buffered Q/V tiles.
// CTA = 128 t-rows (8 warps), 64-col s-tiles. K in dedicated smem region,
// fragments hoisted once. 4-way split-K -> 512 CTAs descending by work.
// ---------------------------------------------------------------------------
#define ATT_SMEM (98304 + 1024)
__global__ __launch_bounds__(256)
void attn_mma_kernel()
{
    extern __shared__ char dsm[];
    char* smc = (char*)(((uintptr_t)dsm + 1023) & ~(uintptr_t)1023);
    const uint32_t sa_b = smem_u32(smc);
    // layout: K hi [0,16K), K lo [16K,32K); buffers at 32K and 64K:
    //   each buffer: Qhi +0, Qlo +8K, Vhi +16K, Vlo +24K

    const int tid = threadIdx.x;
    const int wid = tid >> 5, lane = tid & 31;
    const int g = lane >> 2, t = lane & 3;
    const int R = 16 * wid;

    const int bid   = blockIdx.x;               // 0..511
    const int bt    = 31 - (bid >> 4);          // descending work order
    const int sub   = bid & 15;
    const int b     = sub >> 2;
    const int split = sub & 3;
    const int n     = 2 * bt + 2;
    const int st_lo = (split * n) >> 2;
    const int st_hi = (((split + 1) * n) >> 2) - 1;

    const size_t Rg = (size_t)b * TT + (size_t)bt * 128;
    const size_t vb = (size_t)b * HH * TT;
    const size_t qb = (size_t)b * TT;
    const int trow1 = bt * 128 + R + g;
    const int trow2 = trow1 + 8;

    // ---- stage K (128 rows hi/lo) into its dedicated region; hoist fragments ----
    {
        int r = tid >> 1, half = tid & 1;
        const char* gph = (const char*)(g_Khi + (Rg + r) * HH + half * 32);
        const char* gpl = (const char*)(g_Klo + (Rg + r) * HH + half * 32);
#pragma unroll
        for (int i = 0; i < 4; i++) {
            uint4 vh = *(const uint4*)(gph + 16 * i);
            uint4 vl = *(const uint4*)(gpl + 16 * i);
            uint32_t off = swz((uint32_t)(r * 128 + half * 64 + 16 * i));
            *(uint4*)(smc + off) = vh;
            *(uint4*)(smc + 16384 + off) = vl;
        }
    }
    __syncthreads();
    uint32_t kfh[4][4], kfl[4][4];
#pragma unroll
    for (int kk = 0; kk < 4; kk++) {
        ldA(kfh[kk], smc, R, g, t, kk);
        ldA(kfl[kk], smc + 16384, R, g, t, kk);
    }

    float dO[8][4] = {};
    float m1 = -CUDART_INF_F, m2 = -CUDART_INF_F, l1 = 0.f, l2 = 0.f;

    if (st_lo <= st_hi) {
        // prologue prefetch
        {
            uint32_t bb = sa_b + 32768;
            cp_tile64(g_Qhi + (qb + (size_t)st_lo * 64) * HH, HH, bb, tid);
            cp_tile64(g_Qlo + (qb + (size_t)st_lo * 64) * HH, HH, bb + 8192, tid);
            cp_tile64(g_Vthi + vb + st_lo * 64, TT, bb + 16384, tid);
            cp_tile64(g_Vtlo + vb + st_lo * 64, TT, bb + 24576, tid);
            CP_COMMIT();
        }
#pragma unroll 1
        for (int st = st_lo; st <= st_hi; st++) {
            const int cur = (st - st_lo) & 1;
            const uint32_t cb = sa_b + 32768 + (uint32_t)cur * 32768;
            if (st < st_hi) {
                uint32_t nb = sa_b + 32768 + (uint32_t)(cur ^ 1) * 32768;
                cp_tile64(g_Qhi + (qb + (size_t)(st + 1) * 64) * HH, HH, nb, tid);
                cp_tile64(g_Qlo + (qb + (size_t)(st + 1) * 64) * HH, HH, nb + 8192, tid);
                cp_tile64(g_Vthi + vb + (st + 1) * 64, TT, nb + 16384, tid);
                cp_tile64(g_Vtlo + vb + (st + 1) * 64, TT, nb + 24576, tid);
                CP_COMMIT();
                CP_WAIT(1);
            } else {
                CP_WAIT(0);
            }
            __syncthreads();
            const uint32_t qhi_b = cb, qlo_b = cb + 8192;
            const uint32_t vhi_b = cb + 16384, vlo_b = cb + 24576;

            // ---- S = K @ Q^T ----
            float dS[8][4] = {};
#pragma unroll
            for (int kk = 0; kk < 4; kk++) {
#pragma unroll
                for (int jp = 0; jp < 4; jp++) {
                    uint32_t qh[4], ql[4];
                    ldB4(qh, qhi_b, 2 * jp, kk);
                    ldB4(ql, qlo_b, 2 * jp, kk);
                    uint32_t bh0[2] = { qh[0], qh[1] }, bl0[2] = { ql[0], ql[1] };
                    uint32_t bh1[2] = { qh[2], qh[3] }, bl1[2] = { ql[2], ql[3] };
                    mma3(dS[2 * jp],     kfh[kk], kfl[kk], bh0, bl0);
                    mma3(dS[2 * jp + 1], kfh[kk], kfl[kk], bh1, bl1);
                }
            }

            // ---- scale + causal mask ----
            if (st >= 2 * bt) {
#pragma unroll
                for (int j = 0; j < 8; j++) {
                    int c0 = st * 64 + 8 * j + 2 * t;
                    dS[j][0] = (c0     <= trow1) ? dS[j][0] * 0.125f : -1e30f;
                    dS[j][1] = (c0 + 1 <= trow1) ? dS[j][1] * 0.125f : -1e30f;
                    dS[j][2] = (c0     <= trow2) ? dS[j][2] * 0.125f : -1e30f;
                    dS[j][3] = (c0 + 1 <= trow2) ? dS[j][3] * 0.125f : -1e30f;
                }
            } else {
#pragma unroll
                for (int j = 0; j < 8; j++) {
                    dS[j][0] *= 0.125f; dS[j][1] *= 0.125f;
                    dS[j][2] *= 0.125f; dS[j][3] *= 0.125f;
                }
            }

            // ---- online softmax ----
            float rmax1 = -CUDART_INF_F, rmax2 = -CUDART_INF_F;
#pragma unroll
            for (int j = 0; j < 8; j++) {
                rmax1 = fmaxf(rmax1, fmaxf(dS[j][0], dS[j][1]));
                rmax2 = fmaxf(rmax2, fmaxf(dS[j][2], dS[j][3]));
            }
            rmax1 = fmaxf(rmax1, __shfl_xor_sync(0xffffffffu, rmax1, 1));
            rmax1 = fmaxf(rmax1, __shfl_xor_sync(0xffffffffu, rmax1, 2));
            rmax2 = fmaxf(rmax2, __shfl_xor_sync(0xffffffffu, rmax2, 1));
            rmax2 = fmaxf(rmax2, __shfl_xor_sync(0xffffffffu, rmax2, 2));

            float mn1 = fmaxf(m1, rmax1), mn2 = fmaxf(m2, rmax2);
            float corr1 = __expf(m1 - mn1), corr2 = __expf(m2 - mn2);
            m1 = mn1; m2 = mn2;

            float sum1 = 0.f, sum2 = 0.f;
#pragma unroll
            for (int j = 0; j < 8; j++) {
                dS[j][0] = __expf(dS[j][0] - mn1);
                dS[j][1] = __expf(dS[j][1] - mn1);
                dS[j][2] = __expf(dS[j][2] - mn2);
                dS[j][3] = __expf(dS[j][3] - mn2);
                sum1 += dS[j][0] + dS[j][1];
                sum2 += dS[j][2] + dS[j][3];
            }
            sum1 += __shfl_xor_sync(0xffffffffu, sum1, 1);
            sum1 += __shfl_xor_sync(0xffffffffu, sum1, 2);
            sum2 += __shfl_xor_sync(0xffffffffu, sum2, 1);
            sum2 += __shfl_xor_sync(0xffffffffu, sum2, 2);
            l1 = l1 * corr1 + sum1;
            l2 = l2 * corr2 + sum2;
#pragma unroll
            for (int j = 0; j < 8; j++) {
                dO[j][0] *= corr1; dO[j][1] *= corr1;
                dO[j][2] *= corr2; dO[j][3] *= corr2;
            }

            // ---- O += P @ V (P fragments repacked in registers) ----
#pragma unroll
            for (int ss = 0; ss < 4; ss++) {
                uint32_t pah[4], pal[4];
                bf_split2(dS[2*ss][0],   dS[2*ss][1],   pah[0], pal[0]);
                bf_split2(dS[2*ss][2],   dS[2*ss][3],   pah[1], pal[1]);
                bf_split2(dS[2*ss+1][0], dS[2*ss+1][1], pah[2], pal[2]);
                bf_split2(dS[2*ss+1][2], dS[2*ss+1][3], pah[3], pal[3]);
#pragma unroll
                for (int jp = 0; jp < 4; jp++) {
                    uint32_t vh[4], vl[4];
                    ldB4(vh, vhi_b, 2 * jp, ss);
                    ldB4(vl, vlo_b, 2 * jp, ss);
                    uint32_t bh0[2] = { vh[0], vh[1] }, bl0[2] = { vl[0], vl[1] };
                    uint32_t bh1[2] = { vh[2], vh[3] }, bl1[2] = { vl[2], vl[3] };
                    mma3(dO[2 * jp],     pah, pal, bh0, bl0);
                    mma3(dO[2 * jp + 1], pah, pal, bh1, bl1);
                }
            }
            __syncthreads();   // reads of cb done before it is refilled
        }
    }

    // ---- write unnormalized partial + (m, l) ----
    const size_t orow1 = (size_t)split * NROW + Rg + R + g;
    const size_t orow2 = orow1 + 8;
#pragma unroll
    for (int j = 0; j < 8; j++) {
        int c = 8 * j + 2 * t;
        *(float2*)(g_Oa + orow1 * HH + c) = make_float2(dO[j][0], dO[j][1]);
        *(float2*)(g_Oa + orow2 * HH + c) = make_float2(dO[j][2], dO[j][3]);
    }
    if (t == 0) {
        g_M[orow1] = m1; g_L[orow1] = l1;
        g_M[orow2] = m2; g_L[orow2] = l2;
    }
}

// ---------------------------------------------------------------------------
// Merge the four split partials.
// ---------------------------------------------------------------------------
__global__ __launch_bounds__(256)
void combine_kernel(float* __restrict__ out)
{
    int gid = blockIdx.x * 256 + threadIdx.x;
    int r = gid >> 4, lane = gid & 15;
    float m[NSPLIT], l[NSPLIT];
#pragma unroll
    for (int i = 0; i < NSPLIT; i++) {
        m[i] = g_M[(size_t)i * NROW + r];
        l[i] = g_L[(size_t)i * NROW + r];
    }
    float M = fmaxf(fmaxf(m[0], m[1]), fmaxf(m[2], m[3]));
    float denom = 0.f, e[NSPLIT];
#pragma unroll
    for (int i = 0; i < NSPLIT; i++) {
        e[i] = __expf(m[i] - M);
        denom += l[i] * e[i];
    }
    float inv = 1.0f / denom;
    float4 acc = make_float4(0.f, 0.f, 0.f, 0.f);
#pragma unroll
    for (int i = 0; i < NSPLIT; i++) {
        float4 a = *(const float4*)(g_Oa + ((size_t)i * NROW + r) * HH + 4 * lane);
        acc.x += a.x * e[i]; acc.y += a.y * e[i];
        acc.z += a.z * e[i]; acc.w += a.w * e[i];
    }
    acc.x *= inv; acc.y *= inv; acc.z *= inv; acc.w *= inv;
    *(float4*)(out + (size_t)r * HH + 4 * lane) = acc;
}

extern "C" void kernel_launch(void* const* d_in, const int* in_sizes, int n_in,
                              void* d_out, int out_size)
{
    const float* x  = (const float*)d_in[0];
    const float* Wk = (const float*)d_in[1];
    const float* bk = (const float*)d_in[2];
    const float* Wq = (const float*)d_in[3];
    const float* bq = (const float*)d_in[4];
    const float* Wv = (const float*)d_in[5];
    const float* bv = (const float*)d_in[6];
    float* out = (float*)d_out;

    static bool attr_done = false;
    if (!attr_done) {
        cudaFuncSetAttribute(qkv_kernel,
            cudaFuncAttributeMaxDynamicSharedMemorySize, QKV_SMEM);
        cudaFuncSetAttribute(attn_mma_kernel,
            cudaFuncAttributeMaxDynamicSharedMemorySize, ATT_SMEM);
        attr_done = true;
    }

    cvt_w_kernel<<<24, 128>>>(Wk, Wq, Wv);

    qkv_kernel<<<NROW / 64, 256, QKV_SMEM>>>(x, bk, bq, bv);

    attn_mma_kernel<<<512, 256, ATT_SMEM>>>();

    combine_kernel<<<NROW * 16 / 256, 256>>>(out);
}